// round 5
// baseline (speedup 1.0000x reference)
#include <cuda_runtime.h>

// Problem constants
#define TT 2048          // sequence length
#define DD 64            // head dim
#define CCH 1024         // channels
#define HH 16            // heads
#define BBATCH 4         // batch
#define BHN (BBATCH*HH)  // 64 (b*h)
#define MM (BBATCH*TT)   // 8192 rows

// Scratch: device globals (no runtime allocation allowed)
__device__ __align__(256) float g_q[(size_t)BHN * TT * DD];   // [b,h,t,d]
__device__ __align__(256) float g_k[(size_t)BHN * TT * DD];
__device__ __align__(256) float g_v[(size_t)BHN * TT * DD];
__device__ __align__(256) float g_y[(size_t)MM * CCH];        // [b,t,c]

// ---------------------------------------------------------------------------
// SGEMM: C[M,N] = A[M,K] @ B[K,N], fp32. BM=BN=128, BK=8, 256 thr, 8x8/thread.
// EPI==1: scatter epilogue into g_q/g_k/g_v in [b,h,t,d] layout (QKV GEMM).
// EPI==0: plain row-major epilogue into Cmat; A is overridden to g_y (proj).
// All dims divide tiles exactly for this problem; no bounds checks.
// ---------------------------------------------------------------------------
template <int EPI>
__global__ void __launch_bounds__(256) sgemm_kernel(
    const float* __restrict__ A, const float* __restrict__ B,
    float* __restrict__ Cmat, int N, int K)
{
    __shared__ __align__(16) float As[8][128];
    __shared__ __align__(16) float Bs[8][128];

    const int tid  = threadIdx.x;
    const int m0   = blockIdx.y * 128;
    const int n0   = blockIdx.x * 128;
    const int trow = tid >> 4;           // 0..15
    const int tcol = tid & 15;           // 0..15

    const int a_row = tid >> 1;          // 0..127
    const int a_kc  = (tid & 1) << 2;    // 0 or 4
    const int b_kr  = tid >> 5;          // 0..7
    const int b_nc  = (tid & 31) << 2;   // 0..124

    if (EPI == 0) A = g_y;               // proj GEMM reads attention output

    const float* Aptr = A + (size_t)(m0 + a_row) * K + a_kc;
    const float* Bptr = B + (size_t)b_kr * N + n0 + b_nc;

    float acc[8][8];
#pragma unroll
    for (int i = 0; i < 8; i++)
#pragma unroll
        for (int j = 0; j < 8; j++) acc[i][j] = 0.f;

    for (int k0 = 0; k0 < K; k0 += 8) {
        float4 av = *(const float4*)(Aptr + k0);
        float4 bv = *(const float4*)(Bptr + (size_t)k0 * N);
        As[a_kc + 0][a_row] = av.x;
        As[a_kc + 1][a_row] = av.y;
        As[a_kc + 2][a_row] = av.z;
        As[a_kc + 3][a_row] = av.w;
        *(float4*)&Bs[b_kr][b_nc] = bv;
        __syncthreads();

#pragma unroll
        for (int kk = 0; kk < 8; kk++) {
            float a[8], b[8];
            float4 t0 = *(const float4*)&As[kk][trow * 8];
            float4 t1 = *(const float4*)&As[kk][trow * 8 + 4];
            a[0] = t0.x; a[1] = t0.y; a[2] = t0.z; a[3] = t0.w;
            a[4] = t1.x; a[5] = t1.y; a[6] = t1.z; a[7] = t1.w;
            float4 u0 = *(const float4*)&Bs[kk][tcol * 8];
            float4 u1 = *(const float4*)&Bs[kk][tcol * 8 + 4];
            b[0] = u0.x; b[1] = u0.y; b[2] = u0.z; b[3] = u0.w;
            b[4] = u1.x; b[5] = u1.y; b[6] = u1.z; b[7] = u1.w;
#pragma unroll
            for (int i = 0; i < 8; i++)
#pragma unroll
                for (int j = 0; j < 8; j++)
                    acc[i][j] = fmaf(a[i], b[j], acc[i][j]);
        }
        __syncthreads();
    }

    if (EPI == 0) {
        // plain row-major store
#pragma unroll
        for (int i = 0; i < 8; i++) {
            int mm = m0 + trow * 8 + i;
            float* cp = Cmat + (size_t)mm * N + n0 + tcol * 8;
            *(float4*)(cp)     = make_float4(acc[i][0], acc[i][1], acc[i][2], acc[i][3]);
            *(float4*)(cp + 4) = make_float4(acc[i][4], acc[i][5], acc[i][6], acc[i][7]);
        }
    } else {
        // scatter into q/k/v [b,h,t,d]. n-range of one thread's 8 cols stays
        // inside one head (8 | 64) and one section (128 | 1024).
        int n   = n0 + tcol * 8;
        int sec = n >> 10;           // 0=q 1=k 2=v
        int cc  = n & 1023;
        int h   = cc >> 6;
        int dd  = cc & 63;
        float* base = (sec == 0) ? g_q : (sec == 1) ? g_k : g_v;
#pragma unroll
        for (int i = 0; i < 8; i++) {
            int mm = m0 + trow * 8 + i;
            int bb = mm >> 11;       // / 2048
            int tt = mm & 2047;
            float* cp = base + (((size_t)(bb * HH + h) * TT + tt) * DD + dd);
            *(float4*)(cp)     = make_float4(acc[i][0], acc[i][1], acc[i][2], acc[i][3]);
            *(float4*)(cp + 4) = make_float4(acc[i][4], acc[i][5], acc[i][6], acc[i][7]);
        }
    }
}

// ---------------------------------------------------------------------------
// Flash attention, causal. One thread = one query row (q[64], o[64] in regs).
// CTA: 128 threads = 128 query rows. K/V staged in smem in 64-key tiles;
// per-key K/V row reads are warp-uniform -> broadcast LDS.128 (conflict-free).
// Online softmax with rescale-only-on-new-max (O(log t) rescales per row).
// Fully masked key tiles are never visited.
// ---------------------------------------------------------------------------
__global__ void attn_kernel()
{
    __shared__ __align__(16) float Ksh[64 * DD];
    __shared__ __align__(16) float Vsh[64 * DD];

    const int qi  = (int)gridDim.x - 1 - (int)blockIdx.x;  // heavy tiles first
    const int bh  = blockIdx.y;                             // 0..63
    const int tid = threadIdx.x;                            // 0..127
    const int row = qi * 128 + tid;                         // query index

    const float* qp = g_q + ((size_t)bh * TT + row) * DD;
    float q[64];
#pragma unroll
    for (int i = 0; i < 16; i++) {
        float4 v4 = ((const float4*)qp)[i];
        q[4 * i + 0] = v4.x; q[4 * i + 1] = v4.y;
        q[4 * i + 2] = v4.z; q[4 * i + 3] = v4.w;
    }

    float o[64];
#pragma unroll
    for (int i = 0; i < 64; i++) o[i] = 0.f;
    float m = -1e30f, l = 0.f;

    const int nkt = 2 * qi + 2;   // key tiles with any unmasked entry
    for (int kt = 0; kt < nkt; kt++) {
        const int j0 = kt * 64;
        const float4* kp = (const float4*)(g_k + ((size_t)bh * TT + j0) * DD);
        const float4* vp = (const float4*)(g_v + ((size_t)bh * TT + j0) * DD);
#pragma unroll
        for (int u = 0; u < 8; u++) {
            int idx = u * 128 + tid;            // 1024 float4s, 8 per thread
            ((float4*)Ksh)[idx] = kp[idx];
            ((float4*)Vsh)[idx] = vp[idx];
        }
        __syncthreads();

        int jmax = row - j0 + 1;                // valid keys in this tile
        if (jmax > 64) jmax = 64;
        for (int kk = 0; kk < jmax; kk++) {
            const float4* kr = (const float4*)(Ksh + kk * DD);
            float s0 = 0.f, s1 = 0.f, s2 = 0.f, s3 = 0.f;
#pragma unroll
            for (int i = 0; i < 16; i++) {
                float4 k4 = kr[i];
                s0 = fmaf(q[4 * i + 0], k4.x, s0);
                s1 = fmaf(q[4 * i + 1], k4.y, s1);
                s2 = fmaf(q[4 * i + 2], k4.z, s2);
                s3 = fmaf(q[4 * i + 3], k4.w, s3);
            }
            float s = ((s0 + s1) + (s2 + s3)) * 0.125f;   // d^-0.5 = 1/8
            if (s > m) {
                float corr = __expf(m - s);
                m = s;
                l *= corr;
#pragma unroll
                for (int i = 0; i < 64; i++) o[i] *= corr;
            }
            float p = __expf(s - m);
            l += p;
            const float4* vr = (const float4*)(Vsh + kk * DD);
#pragma unroll
            for (int i = 0; i < 16; i++) {
                float4 v4 = vr[i];
                o[4 * i + 0] = fmaf(p, v4.x, o[4 * i + 0]);
                o[4 * i + 1] = fmaf(p, v4.y, o[4 * i + 1]);
                o[4 * i + 2] = fmaf(p, v4.z, o[4 * i + 2]);
                o[4 * i + 3] = fmaf(p, v4.w, o[4 * i + 3]);
            }
        }
        __syncthreads();
    }

    const float inv = 1.f / l;
    const int bb = bh >> 4;
    const int h  = bh & 15;
    float* yp = g_y + ((size_t)bb * TT + row) * CCH + h * DD;
#pragma unroll
    for (int i = 0; i < 16; i++) {
        ((float4*)yp)[i] = make_float4(o[4 * i + 0] * inv, o[4 * i + 1] * inv,
                                       o[4 * i + 2] * inv, o[4 * i + 3] * inv);
    }
}

// ---------------------------------------------------------------------------
extern "C" void kernel_launch(void* const* d_in, const int* in_sizes, int n_in,
                              void* d_out, int out_size)
{
    const float* x      = (const float*)d_in[0];   // [4,2048,1024]
    const float* w_qkv  = (const float*)d_in[1];   // [1024,3072]
    const float* w_proj = (const float*)d_in[2];   // [1024,1024]
    float* out          = (float*)d_out;           // [4,2048,1024]

    // 1) QKV GEMM with scatter into [b,h,t,d] q/k/v scratch
    {
        dim3 grid(3 * CCH / 128, MM / 128);        // (24, 64)
        sgemm_kernel<1><<<grid, 256>>>(x, w_qkv, nullptr, 3 * CCH, CCH);
    }
    // 2) Causal flash attention -> g_y [b,t,c]
    {
        dim3 grid(TT / 128, BHN);                  // (16, 64)
        attn_kernel<<<grid, 128>>>();
    }
    // 3) Output projection: g_y @ w_proj -> out
    {
        dim3 grid(CCH / 128, MM / 128);            // (8, 64)
        sgemm_kernel<0><<<grid, 256>>>(nullptr, w_proj, out, CCH, CCH);
    }
}

// round 7
// speedup vs baseline: 1.6177x; 1.6177x over previous
#include <cuda_runtime.h>
#include <cuda_bf16.h>

typedef unsigned int u32;
typedef unsigned long long u64;

#define TT 2048
#define DD 64
#define CCH 1024
#define HH 16
#define BB 4
#define BHN (BB*HH)
#define MM (BB*TT)
#define KDIM 1024

// ------------------------- scratch (device globals) -------------------------
__device__ __align__(1024) float g_q[(size_t)BHN * TT * DD];   // [b,h,t,d]
__device__ __align__(1024) float g_k[(size_t)BHN * TT * DD];
__device__ __align__(1024) float g_v[(size_t)BHN * TT * DD];
__device__ __align__(1024) float g_y[(size_t)MM * CCH];        // [b,t,c]

__device__ __align__(1024) __nv_bfloat16 g_xh[(size_t)MM * KDIM];
__device__ __align__(1024) __nv_bfloat16 g_xl[(size_t)MM * KDIM];
__device__ __align__(1024) __nv_bfloat16 g_yh[(size_t)MM * KDIM];
__device__ __align__(1024) __nv_bfloat16 g_yl[(size_t)MM * KDIM];
__device__ __align__(1024) __nv_bfloat16 g_wqh[(size_t)3 * CCH * KDIM]; // w_qkv^T hi
__device__ __align__(1024) __nv_bfloat16 g_wql[(size_t)3 * CCH * KDIM];
__device__ __align__(1024) __nv_bfloat16 g_wph[(size_t)CCH * KDIM];     // w_proj^T hi
__device__ __align__(1024) __nv_bfloat16 g_wpl[(size_t)CCH * KDIM];

// ------------------------- PTX helpers -------------------------
__device__ __forceinline__ u32 smem_u32(const void* p) {
    u32 a;
    asm("{ .reg .u64 t; cvta.to.shared.u64 t, %1; cvt.u32.u64 %0, t; }" : "=r"(a) : "l"(p));
    return a;
}

#define CP_ASYNC16(dst, src) \
    asm volatile("cp.async.cg.shared.global [%0], [%1], 16;" :: "r"(dst), "l"(src) : "memory")
#define CP_COMMIT() asm volatile("cp.async.commit_group;" ::: "memory")
#define CP_WAIT(n)  asm volatile("cp.async.wait_group %0;" :: "n"(n) : "memory")

#define LDSM4(r, addr) \
    asm volatile("ldmatrix.sync.aligned.m8n8.x4.shared.b16 {%0,%1,%2,%3}, [%4];" \
        : "=r"((r)[0]), "=r"((r)[1]), "=r"((r)[2]), "=r"((r)[3]) : "r"(addr))

#define MMA16816(d, a, b0, b1) \
    asm volatile("mma.sync.aligned.m16n8k16.row.col.f32.bf16.bf16.f32 " \
        "{%0,%1,%2,%3}, {%4,%5,%6,%7}, {%8,%9}, {%0,%1,%2,%3};" \
        : "+f"((d)[0]), "+f"((d)[1]), "+f"((d)[2]), "+f"((d)[3]) \
        : "r"((a)[0]), "r"((a)[1]), "r"((a)[2]), "r"((a)[3]), "r"(b0), "r"(b1))

// packed f32x2 math (attention)
#define FMA2(d, a, b) asm("fma.rn.f32x2 %0, %1, %2, %0;" : "+l"(d) : "l"(a), "l"(b))
#define MUL2(d, a, b) asm("mul.rn.f32x2 %0, %1, %2;" : "=l"(d) : "l"(a), "l"(b))
#define PK(d, lo, hi) asm("mov.b64 %0, {%1, %2};" : "=l"(d) : "f"(lo), "f"(hi))
#define UNPK(lo, hi, s) asm("mov.b64 {%0, %1}, %2;" : "=f"(lo), "=f"(hi) : "l"(s))

// ------------------------- fp32 -> bf16 hi/lo split -------------------------
__global__ void __launch_bounds__(256) split_kernel(const float* __restrict__ src,
                                                    __nv_bfloat16* __restrict__ hi,
                                                    __nv_bfloat16* __restrict__ lo, int n4)
{
    int i = blockIdx.x * 256 + threadIdx.x;
    if (i >= n4) return;
    float4 v = ((const float4*)src)[i];
    __nv_bfloat16 h0 = __float2bfloat16_rn(v.x);
    __nv_bfloat16 h1 = __float2bfloat16_rn(v.y);
    __nv_bfloat16 h2 = __float2bfloat16_rn(v.z);
    __nv_bfloat16 h3 = __float2bfloat16_rn(v.w);
    __nv_bfloat16 l0 = __float2bfloat16_rn(v.x - __bfloat162float(h0));
    __nv_bfloat16 l1 = __float2bfloat16_rn(v.y - __bfloat162float(h1));
    __nv_bfloat16 l2 = __float2bfloat16_rn(v.z - __bfloat162float(h2));
    __nv_bfloat16 l3 = __float2bfloat16_rn(v.w - __bfloat162float(h3));
    ((__nv_bfloat162*)hi)[2 * i]     = __nv_bfloat162(h0, h1);
    ((__nv_bfloat162*)hi)[2 * i + 1] = __nv_bfloat162(h2, h3);
    ((__nv_bfloat162*)lo)[2 * i]     = __nv_bfloat162(l0, l1);
    ((__nv_bfloat162*)lo)[2 * i + 1] = __nv_bfloat162(l2, l3);
}

// ------------------------- weight transpose + split -------------------------
// W [KDIM][Ndim] -> Wt_hi/lo [Ndim][KDIM]
__global__ void __launch_bounds__(256) transpose_split(const float* __restrict__ W,
                                                       __nv_bfloat16* __restrict__ dh,
                                                       __nv_bfloat16* __restrict__ dl, int Ndim)
{
    __shared__ float tile[32][33];
    const int n0 = blockIdx.x * 32;
    const int k0 = blockIdx.y * 32;
    const int tx = threadIdx.x & 31;
    const int ty = threadIdx.x >> 5;
#pragma unroll
    for (int r = 0; r < 4; r++)
        tile[ty + 8 * r][tx] = W[(size_t)(k0 + ty + 8 * r) * Ndim + n0 + tx];
    __syncthreads();
#pragma unroll
    for (int r = 0; r < 4; r++) {
        float v = tile[tx][ty + 8 * r];
        __nv_bfloat16 h = __float2bfloat16_rn(v);
        __nv_bfloat16 l = __float2bfloat16_rn(v - __bfloat162float(h));
        size_t idx = (size_t)(n0 + ty + 8 * r) * KDIM + k0 + tx;
        dh[idx] = h;
        dl[idx] = l;
    }
}

// ------------------------- bf16-split tensor-core GEMM -------------------------
// C[M, Nout] = A[M,1024] @ W; A given as hi/lo bf16, W^T as hi/lo bf16 [N][K].
// Tile 128x128, BK=32, 8 warps (warp tile 32x64), double-buffered cp.async.
// 3 MMAs per fragment pair: hh + hl + lh  (ll dropped, ~2^-18).
#define BK 32
#define NCH (KDIM / BK)
#define ROWB 80                     // 40 bf16 per smem row (32 data + 8 pad)
#define TILEB (128 * ROWB)          // 10240 bytes
#define STAGEB (4 * TILEB)          // Ah, Al, Bh, Bl
#define GSMEM (2 * STAGEB)          // 81920 bytes

template <int EPI>   // 1: scatter to g_q/g_k/g_v; 0: plain store to C
__global__ void __launch_bounds__(256) gemm_bf16s(
    const __nv_bfloat16* __restrict__ Ah, const __nv_bfloat16* __restrict__ Al,
    const __nv_bfloat16* __restrict__ Bh, const __nv_bfloat16* __restrict__ Bl,
    float* __restrict__ C, int Nout)
{
    extern __shared__ char smem[];
    const u32 sb   = smem_u32(smem);
    const int tid  = threadIdx.x;
    const int lane = tid & 31;
    const int wid  = tid >> 5;
    const int wm   = wid & 3;            // M block of 32
    const int wn   = wid >> 2;           // N block of 64
    const int m0   = blockIdx.y * 128;
    const int n0   = blockIdx.x * 128;

    // loader mapping: 512 16B-chunks per tile, 2 per thread
    const int ch0  = tid;                // chunk ids tid, tid+256
    auto load_stage = [&](int kc, int stage) {
        const int k0 = kc * BK;
        const u32 s = sb + stage * STAGEB;
#pragma unroll
        for (int r = 0; r < 2; r++) {
            int ch  = ch0 + r * 256;
            int row = ch >> 2;
            int c4  = ch & 3;
            u32 dst = (u32)(row * ROWB + c4 * 16);
            size_t asrc = (size_t)(m0 + row) * KDIM + k0 + c4 * 8;
            size_t bsrc = (size_t)(n0 + row) * KDIM + k0 + c4 * 8;
            CP_ASYNC16(s + dst,              Ah + asrc);
            CP_ASYNC16(s + TILEB + dst,      Al + asrc);
            CP_ASYNC16(s + 2 * TILEB + dst,  Bh + bsrc);
            CP_ASYNC16(s + 3 * TILEB + dst,  Bl + bsrc);
        }
    };

    // ldmatrix per-lane offsets
    const u32 a_off = (u32)((lane & 15) * ROWB + ((lane >> 4) << 4));
    const u32 b_off = (u32)(((((lane >> 4) << 3) + (lane & 7)) * ROWB) + (((lane >> 3) & 1) << 4));

    float acc[2][8][4];
#pragma unroll
    for (int mt = 0; mt < 2; mt++)
#pragma unroll
        for (int nt = 0; nt < 8; nt++)
#pragma unroll
            for (int q = 0; q < 4; q++) acc[mt][nt][q] = 0.f;

    load_stage(0, 0);
    CP_COMMIT();

    for (int i = 0; i < NCH; i++) {
        if (i + 1 < NCH) { load_stage(i + 1, (i + 1) & 1); CP_COMMIT(); CP_WAIT(1); }
        else             { CP_WAIT(0); }
        __syncthreads();

        const u32 s  = sb + (i & 1) * STAGEB;
        const u32 aH = s             + (u32)(wm * 32) * ROWB + a_off;
        const u32 aL = s + TILEB     + (u32)(wm * 32) * ROWB + a_off;
        const u32 bH = s + 2 * TILEB + (u32)(wn * 64) * ROWB + b_off;
        const u32 bL = s + 3 * TILEB + (u32)(wn * 64) * ROWB + b_off;

#pragma unroll
        for (int kt = 0; kt < 2; kt++) {
            const u32 ktb = (u32)kt * 32;          // 16 bf16 = 32 bytes
            u32 ah[2][4], al[2][4];
#pragma unroll
            for (int mt = 0; mt < 2; mt++) {
                LDSM4(ah[mt], aH + (u32)mt * (16 * ROWB) + ktb);
                LDSM4(al[mt], aL + (u32)mt * (16 * ROWB) + ktb);
            }
            u32 bh[4][4], bl[4][4];
#pragma unroll
            for (int p = 0; p < 4; p++) {
                LDSM4(bh[p], bH + (u32)p * (16 * ROWB) + ktb);
                LDSM4(bl[p], bL + (u32)p * (16 * ROWB) + ktb);
            }
#pragma unroll
            for (int mt = 0; mt < 2; mt++)
#pragma unroll
                for (int nt = 0; nt < 8; nt++) {
                    const int p = nt >> 1, e = (nt & 1) * 2;
                    MMA16816(acc[mt][nt], ah[mt], bh[p][e], bh[p][e + 1]);
                    MMA16816(acc[mt][nt], ah[mt], bl[p][e], bl[p][e + 1]);
                    MMA16816(acc[mt][nt], al[mt], bh[p][e], bh[p][e + 1]);
                }
        }
        __syncthreads();
    }

    // epilogue: thread (mt,nt) -> rows r, r+8 ; cols c, c+1
#pragma unroll
    for (int mt = 0; mt < 2; mt++) {
        const int r0 = m0 + wm * 32 + mt * 16 + (lane >> 2);
#pragma unroll
        for (int nt = 0; nt < 8; nt++) {
            const int n = n0 + wn * 64 + nt * 8 + (lane & 3) * 2;
            if (EPI == 0) {
                float* p0 = C + (size_t)r0 * Nout + n;
                float* p1 = C + (size_t)(r0 + 8) * Nout + n;
                *(float2*)p0 = make_float2(acc[mt][nt][0], acc[mt][nt][1]);
                *(float2*)p1 = make_float2(acc[mt][nt][2], acc[mt][nt][3]);
            } else {
                const int sec = n >> 10;          // 0=q 1=k 2=v
                const int cc  = n & 1023;
                const int h   = cc >> 6, dd = cc & 63;
                float* base = (sec == 0) ? g_q : (sec == 1) ? g_k : g_v;
                const int bb0 = r0 >> 11, tt0 = r0 & 2047;
                const int r1 = r0 + 8;
                const int bb1 = r1 >> 11, tt1 = r1 & 2047;
                float* p0 = base + (((size_t)(bb0 * HH + h) * TT + tt0) * DD + dd);
                float* p1 = base + (((size_t)(bb1 * HH + h) * TT + tt1) * DD + dd);
                *(float2*)p0 = make_float2(acc[mt][nt][0], acc[mt][nt][1]);
                *(float2*)p1 = make_float2(acc[mt][nt][2], acc[mt][nt][3]);
            }
        }
    }
}

// ------------------------- flash attention (f32x2 packed math) -------------------------
__global__ void __launch_bounds__(128, 2) attn_kernel()
{
    __shared__ __align__(16) float Ksh[64 * DD];
    __shared__ __align__(16) float Vsh[64 * DD];

    const int qi  = (int)gridDim.x - 1 - (int)blockIdx.x;  // heavy tiles first
    const int bh  = blockIdx.y;
    const int tid = threadIdx.x;
    const int row = qi * 128 + tid;

    const ulonglong2* qp = (const ulonglong2*)(g_q + ((size_t)bh * TT + row) * DD);
    u64 q2[32];
#pragma unroll
    for (int i = 0; i < 16; i++) { ulonglong2 t = qp[i]; q2[2 * i] = t.x; q2[2 * i + 1] = t.y; }

    u64 o2[32];
#pragma unroll
    for (int i = 0; i < 32; i++) o2[i] = 0ULL;
    float m = -1e30f, l = 0.f;

    const int nkt = 2 * qi + 2;
    for (int kt = 0; kt < nkt; kt++) {
        const int j0 = kt * 64;
        const float4* kp = (const float4*)(g_k + ((size_t)bh * TT + j0) * DD);
        const float4* vp = (const float4*)(g_v + ((size_t)bh * TT + j0) * DD);
#pragma unroll
        for (int u = 0; u < 8; u++) {
            int idx = u * 128 + tid;
            ((float4*)Ksh)[idx] = kp[idx];
            ((float4*)Vsh)[idx] = vp[idx];
        }
        __syncthreads();

        int jmax = row - j0 + 1;
        if (jmax > 64) jmax = 64;
        for (int kk = 0; kk < jmax; kk++) {
            const ulonglong2* kr = (const ulonglong2*)(Ksh + kk * DD);
            u64 a0 = 0ULL, a1 = 0ULL;
#pragma unroll
            for (int i = 0; i < 16; i++) {
                ulonglong2 kv = kr[i];
                FMA2(a0, q2[2 * i], kv.x);
                FMA2(a1, q2[2 * i + 1], kv.y);
            }
            float x0, x1, y0, y1;
            UNPK(x0, x1, a0);
            UNPK(y0, y1, a1);
            float s = ((x0 + y0) + (x1 + y1)) * 0.125f;     // d^-0.5 = 1/8
            if (s > m) {
                float corr = __expf(m - s);
                m = s; l *= corr;
                u64 c2; PK(c2, corr, corr);
#pragma unroll
                for (int i = 0; i < 32; i++) MUL2(o2[i], o2[i], c2);
            }
            float p = __expf(s - m);
            l += p;
            u64 p2; PK(p2, p, p);
            const ulonglong2* vr = (const ulonglong2*)(Vsh + kk * DD);
#pragma unroll
            for (int i = 0; i < 16; i++) {
                ulonglong2 vv = vr[i];
                FMA2(o2[2 * i],     p2, vv.x);
                FMA2(o2[2 * i + 1], p2, vv.y);
            }
        }
        __syncthreads();
    }

    const float inv = 1.f / l;
    u64 inv2; PK(inv2, inv, inv);
    const int bb = bh >> 4, h = bh & 15;
    ulonglong2* yp = (ulonglong2*)(g_y + ((size_t)bb * TT + row) * CCH + h * DD);
#pragma unroll
    for (int i = 0; i < 16; i++) {
        u64 z0 = o2[2 * i], z1 = o2[2 * i + 1];
        MUL2(z0, z0, inv2);
        MUL2(z1, z1, inv2);
        yp[i] = make_ulonglong2(z0, z1);
    }
}

// ---------------------------------------------------------------------------
extern "C" void kernel_launch(void* const* d_in, const int* in_sizes, int n_in,
                              void* d_out, int out_size)
{
    const float* x      = (const float*)d_in[0];   // [4,2048,1024]
    const float* w_qkv  = (const float*)d_in[1];   // [1024,3072]
    const float* w_proj = (const float*)d_in[2];   // [1024,1024]
    float* out          = (float*)d_out;           // [4,2048,1024]

    cudaFuncSetAttribute(gemm_bf16s<1>, cudaFuncAttributeMaxDynamicSharedMemorySize, GSMEM);
    cudaFuncSetAttribute(gemm_bf16s<0>, cudaFuncAttributeMaxDynamicSharedMemorySize, GSMEM);

    __nv_bfloat16 *xh, *xl, *yh, *yl, *wqh, *wql, *wph, *wpl;
    cudaGetSymbolAddress((void**)&xh,  g_xh);
    cudaGetSymbolAddress((void**)&xl,  g_xl);
    cudaGetSymbolAddress((void**)&yh,  g_yh);
    cudaGetSymbolAddress((void**)&yl,  g_yl);
    cudaGetSymbolAddress((void**)&wqh, g_wqh);
    cudaGetSymbolAddress((void**)&wql, g_wql);
    cudaGetSymbolAddress((void**)&wph, g_wph);
    cudaGetSymbolAddress((void**)&wpl, g_wpl);
    float* gy;
    cudaGetSymbolAddress((void**)&gy, g_y);

    // 0) operand prep: W -> W^T hi/lo ; x -> hi/lo
    transpose_split<<<dim3(3 * CCH / 32, KDIM / 32), 256>>>(w_qkv, wqh, wql, 3 * CCH);
    transpose_split<<<dim3(CCH / 32, KDIM / 32), 256>>>(w_proj, wph, wpl, CCH);
    split_kernel<<<(MM * KDIM / 4 + 255) / 256, 256>>>(x, xh, xl, MM * KDIM / 4);

    // 1) QKV GEMM (bf16-split tensor core) with scatter into [b,h,t,d]
    gemm_bf16s<1><<<dim3(3 * CCH / 128, MM / 128), 256, GSMEM>>>(xh, xl, wqh, wql, nullptr, 3 * CCH);

    // 2) causal flash attention -> g_y
    attn_kernel<<<dim3(TT / 128, BHN), 128>>>();

    // 3) y -> hi/lo ; output projection
    split_kernel<<<(MM * KDIM / 4 + 255) / 256, 256>>>(gy, yh, yl, MM * KDIM / 4);
    gemm_bf16s<0><<<dim3(CCH / 128, MM / 128), 256, GSMEM>>>(yh, yl, wph, wpl, out, CCH);
}

// round 8
// speedup vs baseline: 2.9123x; 1.8003x over previous
#include <cuda_runtime.h>
#include <cuda_bf16.h>

typedef unsigned int u32;
typedef unsigned long long u64;
typedef unsigned short u16;

#define TT 2048
#define DD 64
#define CCH 1024
#define HH 16
#define BB 4
#define BHN (BB*HH)
#define MM (BB*TT)
#define KDIM 1024

// ------------------------- scratch (device globals) -------------------------
__device__ __align__(1024) __nv_bfloat16 g_xh[(size_t)MM * KDIM];
__device__ __align__(1024) __nv_bfloat16 g_xl[(size_t)MM * KDIM];
__device__ __align__(1024) __nv_bfloat16 g_wqh[(size_t)3 * CCH * KDIM];
__device__ __align__(1024) __nv_bfloat16 g_wql[(size_t)3 * CCH * KDIM];
__device__ __align__(1024) __nv_bfloat16 g_wph[(size_t)CCH * KDIM];
__device__ __align__(1024) __nv_bfloat16 g_wpl[(size_t)CCH * KDIM];

__device__ __align__(1024) __nv_bfloat16 g_qh[(size_t)BHN * TT * DD];  // [b,h,t,d]
__device__ __align__(1024) __nv_bfloat16 g_ql[(size_t)BHN * TT * DD];
__device__ __align__(1024) __nv_bfloat16 g_kh[(size_t)BHN * TT * DD];
__device__ __align__(1024) __nv_bfloat16 g_kl[(size_t)BHN * TT * DD];
__device__ __align__(1024) __nv_bfloat16 g_vh[(size_t)BHN * TT * DD];
__device__ __align__(1024) __nv_bfloat16 g_vl[(size_t)BHN * TT * DD];
__device__ __align__(1024) __nv_bfloat16 g_vth[(size_t)BHN * DD * TT]; // [b,h,d,t]
__device__ __align__(1024) __nv_bfloat16 g_vtl[(size_t)BHN * DD * TT];
__device__ __align__(1024) __nv_bfloat16 g_yh[(size_t)MM * CCH];       // [b,t,c]
__device__ __align__(1024) __nv_bfloat16 g_yl[(size_t)MM * CCH];

// ------------------------- PTX helpers -------------------------
__device__ __forceinline__ u32 smem_u32(const void* p) {
    u32 a;
    asm("{ .reg .u64 t; cvta.to.shared.u64 t, %1; cvt.u32.u64 %0, t; }" : "=r"(a) : "l"(p));
    return a;
}

#define CP_ASYNC16(dst, src) \
    asm volatile("cp.async.cg.shared.global [%0], [%1], 16;" :: "r"(dst), "l"(src) : "memory")
#define CP_COMMIT() asm volatile("cp.async.commit_group;" ::: "memory")
#define CP_WAIT(n)  asm volatile("cp.async.wait_group %0;" :: "n"(n) : "memory")

#define LDSM4(r, addr) \
    asm volatile("ldmatrix.sync.aligned.m8n8.x4.shared.b16 {%0,%1,%2,%3}, [%4];" \
        : "=r"((r)[0]), "=r"((r)[1]), "=r"((r)[2]), "=r"((r)[3]) : "r"(addr))

#define MMA16816(d, a, b0, b1) \
    asm volatile("mma.sync.aligned.m16n8k16.row.col.f32.bf16.bf16.f32 " \
        "{%0,%1,%2,%3}, {%4,%5,%6,%7}, {%8,%9}, {%0,%1,%2,%3};" \
        : "+f"((d)[0]), "+f"((d)[1]), "+f"((d)[2]), "+f"((d)[3]) \
        : "r"((a)[0]), "r"((a)[1]), "r"((a)[2]), "r"((a)[3]), "r"(b0), "r"(b1))

__device__ __forceinline__ u32 pack2bf(__nv_bfloat16 lo, __nv_bfloat16 hi) {
    return (u32)*(u16*)&lo | ((u32)*(u16*)&hi << 16);
}
// split two f32 into packed bf16 hi-pair and lo-pair (lo half = first arg)
__device__ __forceinline__ void split2(float a, float b, u32& hi, u32& lo) {
    __nv_bfloat16 ha = __float2bfloat16_rn(a), hb = __float2bfloat16_rn(b);
    __nv_bfloat16 la = __float2bfloat16_rn(a - __bfloat162float(ha));
    __nv_bfloat16 lb = __float2bfloat16_rn(b - __bfloat162float(hb));
    hi = pack2bf(ha, hb);
    lo = pack2bf(la, lb);
}

// ------------------------- fp32 -> bf16 hi/lo split (x only) -------------------------
__global__ void __launch_bounds__(256) split_kernel(const float* __restrict__ src,
                                                    __nv_bfloat16* __restrict__ hi,
                                                    __nv_bfloat16* __restrict__ lo, int n4)
{
    int i = blockIdx.x * 256 + threadIdx.x;
    if (i >= n4) return;
    float4 v = ((const float4*)src)[i];
    u32 h0, l0, h1, l1;
    split2(v.x, v.y, h0, l0);
    split2(v.z, v.w, h1, l1);
    ((uint2*)hi)[i] = make_uint2(h0, h1);
    ((uint2*)lo)[i] = make_uint2(l0, l1);
}

// ------------------------- weight transpose + split -------------------------
__global__ void __launch_bounds__(256) transpose_split(const float* __restrict__ W,
                                                       __nv_bfloat16* __restrict__ dh,
                                                       __nv_bfloat16* __restrict__ dl, int Ndim)
{
    __shared__ float tile[32][33];
    const int n0 = blockIdx.x * 32;
    const int k0 = blockIdx.y * 32;
    const int tx = threadIdx.x & 31;
    const int ty = threadIdx.x >> 5;
#pragma unroll
    for (int r = 0; r < 4; r++)
        tile[ty + 8 * r][tx] = W[(size_t)(k0 + ty + 8 * r) * Ndim + n0 + tx];
    __syncthreads();
#pragma unroll
    for (int r = 0; r < 4; r++) {
        float v = tile[tx][ty + 8 * r];
        __nv_bfloat16 h = __float2bfloat16_rn(v);
        __nv_bfloat16 l = __float2bfloat16_rn(v - __bfloat162float(h));
        size_t idx = (size_t)(n0 + ty + 8 * r) * KDIM + k0 + tx;
        dh[idx] = h;
        dl[idx] = l;
    }
}

// ------------------------- V transpose: [b,h,t,d] -> [b,h,d,t] (bf16 hi+lo) -----------
__global__ void __launch_bounds__(256) vt_kernel()
{
    __shared__ __nv_bfloat16 sh[64][72];
    __shared__ __nv_bfloat16 sl[64][72];
    const int bh = blockIdx.y;
    const int t0 = blockIdx.x * 64;
    const int tid = threadIdx.x;
#pragma unroll
    for (int k = 0; k < 4; k++) {
        int ch = tid + k * 256;           // 1024 chunks: hi 512 + lo 512
        int hl = ch >> 9, rem = ch & 511;
        int row = rem >> 3, c = rem & 7;  // row = t, c*8 = d
        uint4 v = *(const uint4*)((hl ? g_vl : g_vh) + ((size_t)bh * TT + t0 + row) * DD + c * 8);
        __nv_bfloat16* dst = hl ? &sl[row][c * 8] : &sh[row][c * 8];
        *(uint4*)dst = v;
    }
    __syncthreads();
#pragma unroll
    for (int k = 0; k < 4; k++) {
        int ch = tid + k * 256;
        int hl = ch >> 9, rem = ch & 511;
        int d = rem >> 3, c = rem & 7;    // out row = d, t chunk = c*8
        u32 w[4];
#pragma unroll
        for (int e = 0; e < 4; e++) {
            __nv_bfloat16 a = hl ? sl[c * 8 + 2 * e][d]     : sh[c * 8 + 2 * e][d];
            __nv_bfloat16 b = hl ? sl[c * 8 + 2 * e + 1][d] : sh[c * 8 + 2 * e + 1][d];
            w[e] = pack2bf(a, b);
        }
        __nv_bfloat16* dst = (hl ? g_vtl : g_vth) + ((size_t)bh * DD + d) * TT + t0 + c * 8;
        *(uint4*)dst = make_uint4(w[0], w[1], w[2], w[3]);
    }
}

// ------------------------- bf16-split tensor-core GEMM -------------------------
#define BK 32
#define NCH (KDIM / BK)
#define ROWB 80
#define TILEB (128 * ROWB)
#define STAGEB (4 * TILEB)
#define GSMEM (2 * STAGEB)

template <int EPI>   // 1: split-scatter to g_{q,k,v}{h,l}; 0: fp32 store to C
__global__ void __launch_bounds__(256) gemm_bf16s(
    const __nv_bfloat16* __restrict__ Ah, const __nv_bfloat16* __restrict__ Al,
    const __nv_bfloat16* __restrict__ Bh, const __nv_bfloat16* __restrict__ Bl,
    float* __restrict__ C, int Nout)
{
    extern __shared__ char smem[];
    const u32 sb   = smem_u32(smem);
    const int tid  = threadIdx.x;
    const int lane = tid & 31;
    const int wid  = tid >> 5;
    const int wm   = wid & 3;
    const int wn   = wid >> 2;
    const int m0   = blockIdx.y * 128;
    const int n0   = blockIdx.x * 128;

    auto load_stage = [&](int kc, int stage) {
        const int k0 = kc * BK;
        const u32 s = sb + stage * STAGEB;
#pragma unroll
        for (int r = 0; r < 2; r++) {
            int ch  = tid + r * 256;
            int row = ch >> 2;
            int c4  = ch & 3;
            u32 dst = (u32)(row * ROWB + c4 * 16);
            size_t asrc = (size_t)(m0 + row) * KDIM + k0 + c4 * 8;
            size_t bsrc = (size_t)(n0 + row) * KDIM + k0 + c4 * 8;
            CP_ASYNC16(s + dst,              Ah + asrc);
            CP_ASYNC16(s + TILEB + dst,      Al + asrc);
            CP_ASYNC16(s + 2 * TILEB + dst,  Bh + bsrc);
            CP_ASYNC16(s + 3 * TILEB + dst,  Bl + bsrc);
        }
    };

    const u32 a_off = (u32)((lane & 15) * ROWB + ((lane >> 4) << 4));
    const u32 b_off = (u32)(((((lane >> 4) << 3) + (lane & 7)) * ROWB) + (((lane >> 3) & 1) << 4));

    float acc[2][8][4];
#pragma unroll
    for (int mt = 0; mt < 2; mt++)
#pragma unroll
        for (int nt = 0; nt < 8; nt++)
#pragma unroll
            for (int q = 0; q < 4; q++) acc[mt][nt][q] = 0.f;

    load_stage(0, 0);
    CP_COMMIT();

    for (int i = 0; i < NCH; i++) {
        if (i + 1 < NCH) { load_stage(i + 1, (i + 1) & 1); CP_COMMIT(); CP_WAIT(1); }
        else             { CP_WAIT(0); }
        __syncthreads();

        const u32 s  = sb + (i & 1) * STAGEB;
        const u32 aH = s             + (u32)(wm * 32) * ROWB + a_off;
        const u32 aL = s + TILEB     + (u32)(wm * 32) * ROWB + a_off;
        const u32 bH = s + 2 * TILEB + (u32)(wn * 64) * ROWB + b_off;
        const u32 bL = s + 3 * TILEB + (u32)(wn * 64) * ROWB + b_off;

#pragma unroll
        for (int kt = 0; kt < 2; kt++) {
            const u32 ktb = (u32)kt * 32;
            u32 ah[2][4], al[2][4];
#pragma unroll
            for (int mt = 0; mt < 2; mt++) {
                LDSM4(ah[mt], aH + (u32)mt * (16 * ROWB) + ktb);
                LDSM4(al[mt], aL + (u32)mt * (16 * ROWB) + ktb);
            }
            u32 bh[4][4], bl[4][4];
#pragma unroll
            for (int p = 0; p < 4; p++) {
                LDSM4(bh[p], bH + (u32)p * (16 * ROWB) + ktb);
                LDSM4(bl[p], bL + (u32)p * (16 * ROWB) + ktb);
            }
#pragma unroll
            for (int mt = 0; mt < 2; mt++)
#pragma unroll
                for (int nt = 0; nt < 8; nt++) {
                    const int p = nt >> 1, e = (nt & 1) * 2;
                    MMA16816(acc[mt][nt], ah[mt], bh[p][e], bh[p][e + 1]);
                    MMA16816(acc[mt][nt], ah[mt], bl[p][e], bl[p][e + 1]);
                    MMA16816(acc[mt][nt], al[mt], bh[p][e], bh[p][e + 1]);
                }
        }
        __syncthreads();
    }

#pragma unroll
    for (int mt = 0; mt < 2; mt++) {
        const int r0 = m0 + wm * 32 + mt * 16 + (lane >> 2);
#pragma unroll
        for (int nt = 0; nt < 8; nt++) {
            const int n = n0 + wn * 64 + nt * 8 + (lane & 3) * 2;
            if (EPI == 0) {
                float* p0 = C + (size_t)r0 * Nout + n;
                float* p1 = C + (size_t)(r0 + 8) * Nout + n;
                *(float2*)p0 = make_float2(acc[mt][nt][0], acc[mt][nt][1]);
                *(float2*)p1 = make_float2(acc[mt][nt][2], acc[mt][nt][3]);
            } else {
                const int sec = n >> 10;
                const int cc  = n & 1023;
                const int h   = cc >> 6, dd = cc & 63;
                __nv_bfloat16* bhp = (sec == 0) ? g_qh : (sec == 1) ? g_kh : g_vh;
                __nv_bfloat16* blp = (sec == 0) ? g_ql : (sec == 1) ? g_kl : g_vl;
                const int bb0 = r0 >> 11, tt0 = r0 & 2047;
                const int r1 = r0 + 8;
                const int bb1 = r1 >> 11, tt1 = r1 & 2047;
                size_t i0 = ((size_t)(bb0 * HH + h) * TT + tt0) * DD + dd;
                size_t i1 = ((size_t)(bb1 * HH + h) * TT + tt1) * DD + dd;
                u32 hi, lo;
                split2(acc[mt][nt][0], acc[mt][nt][1], hi, lo);
                *(u32*)(bhp + i0) = hi;  *(u32*)(blp + i0) = lo;
                split2(acc[mt][nt][2], acc[mt][nt][3], hi, lo);
                *(u32*)(bhp + i1) = hi;  *(u32*)(blp + i1) = lo;
            }
        }
    }
}

// ------------------------- tensor-core flash attention -------------------------
// CTA: 256 thr (8 warps), 128 query rows (16/warp), 64-key tiles, double-buffered.
#define AROW 72
#define AROWB 144
#define KTL 64
#define ASTG (4 * KTL * AROWB)     // Kh,Kl,Vth,Vtl = 36864 B
#define ASMEM (2 * ASTG)           // 73728 B

__global__ void __launch_bounds__(256, 1) attn_tc()
{
    extern __shared__ char smem[];
    const u32 sb   = smem_u32(smem);
    const int tid  = threadIdx.x;
    const int lane = tid & 31;
    const int wid  = tid >> 5;
    const int qi   = (int)gridDim.x - 1 - (int)blockIdx.x;  // heavy tiles first
    const int bh   = blockIdx.y;
    const int q0   = qi * 128;
    const int g    = lane >> 2, tg = lane & 3;
    const int wrow0 = q0 + wid * 16;

    // ---- stage Q hi/lo into buf0 ----
#pragma unroll
    for (int r = 0; r < 8; r++) {
        int ch  = tid + r * 256;          // 2048 chunks
        int hl  = ch >> 10;
        int rem = ch & 1023;
        int row = rem >> 3, c = rem & 7;
        const __nv_bfloat16* src = (hl ? g_ql : g_qh) + ((size_t)bh * TT + q0 + row) * DD + c * 8;
        CP_ASYNC16(sb + hl * (128 * AROWB) + row * AROWB + c * 16, src);
    }
    CP_COMMIT();

    auto load_kv = [&](int kt, int buf) {
        const int j0 = kt * KTL;
        const u32 s = sb + buf * ASTG;
#pragma unroll
        for (int r = 0; r < 8; r++) {
            int ch  = tid + r * 256;      // 2048 chunks: 4 mats x 64 rows x 8
            int mat = ch >> 9;
            int rem = ch & 511;
            int row = rem >> 3, c = rem & 7;
            const __nv_bfloat16* src;
            if      (mat == 0) src = g_kh  + ((size_t)bh * TT + j0 + row) * DD + c * 8;
            else if (mat == 1) src = g_kl  + ((size_t)bh * TT + j0 + row) * DD + c * 8;
            else if (mat == 2) src = g_vth + ((size_t)bh * DD + row) * TT + j0 + c * 8;
            else               src = g_vtl + ((size_t)bh * DD + row) * TT + j0 + c * 8;
            CP_ASYNC16(s + mat * (KTL * AROWB) + row * AROWB + c * 16, src);
        }
        CP_COMMIT();
    };

    load_kv(0, 1);
    CP_WAIT(1);                 // Q ready
    __syncthreads();

    // ldmatrix Q A-frags (M=16 per warp, 4 k-steps, hi+lo)
    u32 qh[4][4], ql[4][4];
    {
        const u32 qb = sb + (u32)(wid * 16 + (lane & 15)) * AROWB + ((lane >> 4) << 4);
#pragma unroll
        for (int ks = 0; ks < 4; ks++) {
            LDSM4(qh[ks], qb + ks * 32);
            LDSM4(ql[ks], qb + 128 * AROWB + ks * 32);
        }
    }
    __syncthreads();            // buf0 free for prefetch

    float o[8][4];
#pragma unroll
    for (int nt = 0; nt < 8; nt++)
#pragma unroll
        for (int e = 0; e < 4; e++) o[nt][e] = 0.f;
    float m_lo = -1e30f, m_hi = -1e30f, l_lo = 0.f, l_hi = 0.f;

    const u32 boff = (u32)((((lane >> 4) << 3) + (lane & 7)) * AROWB + (((lane >> 3) & 1) << 4));
    const int nkt = 2 * qi + 2;

    for (int kt = 0; kt < nkt; kt++) {
        if (kt + 1 < nkt) { load_kv(kt + 1, kt & 1); CP_WAIT(1); }
        else              { CP_WAIT(0); }
        __syncthreads();

        const u32 s  = sb + ((kt + 1) & 1) * ASTG;
        const int j0 = kt * KTL;

        if (j0 <= wrow0 + 15) {
            // ---- S = Q K^T (bf16x3) ----
            float sacc[8][4];
#pragma unroll
            for (int nt = 0; nt < 8; nt++)
#pragma unroll
                for (int e = 0; e < 4; e++) sacc[nt][e] = 0.f;
#pragma unroll
            for (int p = 0; p < 4; p++) {
#pragma unroll
                for (int ks = 0; ks < 4; ks++) {
                    u32 kh[4], kl[4];
                    LDSM4(kh, s + (u32)p * (16 * AROWB) + boff + ks * 32);
                    LDSM4(kl, s + KTL * AROWB + (u32)p * (16 * AROWB) + boff + ks * 32);
                    MMA16816(sacc[2 * p],     qh[ks], kh[0], kh[1]);
                    MMA16816(sacc[2 * p],     ql[ks], kh[0], kh[1]);
                    MMA16816(sacc[2 * p],     qh[ks], kl[0], kl[1]);
                    MMA16816(sacc[2 * p + 1], qh[ks], kh[2], kh[3]);
                    MMA16816(sacc[2 * p + 1], ql[ks], kh[2], kh[3]);
                    MMA16816(sacc[2 * p + 1], qh[ks], kl[2], kl[3]);
                }
            }
            // ---- scale + causal mask + row max ----
            const int row_a = wrow0 + g;       // and row_a + 8
            const bool diag = (j0 + 63 > wrow0);
            float tmax_lo = -1e30f, tmax_hi = -1e30f;
#pragma unroll
            for (int nt = 0; nt < 8; nt++) {
#pragma unroll
                for (int e = 0; e < 2; e++) {
                    int j = j0 + nt * 8 + tg * 2 + e;
                    float v0 = sacc[nt][e]     * 0.125f;
                    float v1 = sacc[nt][e + 2] * 0.125f;
                    if (diag) {
                        if (j > row_a)     v0 = -1e30f;
                        if (j > row_a + 8) v1 = -1e30f;
                    }
                    sacc[nt][e]     = v0;
                    sacc[nt][e + 2] = v1;
                    tmax_lo = fmaxf(tmax_lo, v0);
                    tmax_hi = fmaxf(tmax_hi, v1);
                }
            }
            tmax_lo = fmaxf(tmax_lo, __shfl_xor_sync(0xffffffffu, tmax_lo, 1));
            tmax_lo = fmaxf(tmax_lo, __shfl_xor_sync(0xffffffffu, tmax_lo, 2));
            tmax_hi = fmaxf(tmax_hi, __shfl_xor_sync(0xffffffffu, tmax_hi, 1));
            tmax_hi = fmaxf(tmax_hi, __shfl_xor_sync(0xffffffffu, tmax_hi, 2));

            float mn_lo = fmaxf(m_lo, tmax_lo);
            float mn_hi = fmaxf(m_hi, tmax_hi);
            float c_lo = __expf(m_lo - mn_lo);
            float c_hi = __expf(m_hi - mn_hi);
            m_lo = mn_lo; m_hi = mn_hi;
            l_lo *= c_lo; l_hi *= c_hi;
#pragma unroll
            for (int nt = 0; nt < 8; nt++) {
                o[nt][0] *= c_lo; o[nt][1] *= c_lo;
                o[nt][2] *= c_hi; o[nt][3] *= c_hi;
            }
            // ---- P = exp(S - m), split to A-frags ----
            u32 ph[4][4], pl[4][4];
            float rs_lo = 0.f, rs_hi = 0.f;
#pragma unroll
            for (int kk = 0; kk < 4; kk++) {
#pragma unroll
                for (int half = 0; half < 2; half++) {
                    const int t2 = 2 * kk + half;
                    float p0 = __expf(sacc[t2][0] - m_lo);
                    float p1 = __expf(sacc[t2][1] - m_lo);
                    float p2 = __expf(sacc[t2][2] - m_hi);
                    float p3 = __expf(sacc[t2][3] - m_hi);
                    rs_lo += p0 + p1;  rs_hi += p2 + p3;
                    split2(p0, p1, ph[kk][2 * half],     pl[kk][2 * half]);
                    split2(p2, p3, ph[kk][2 * half + 1], pl[kk][2 * half + 1]);
                }
            }
            rs_lo += __shfl_xor_sync(0xffffffffu, rs_lo, 1);
            rs_lo += __shfl_xor_sync(0xffffffffu, rs_lo, 2);
            rs_hi += __shfl_xor_sync(0xffffffffu, rs_hi, 1);
            rs_hi += __shfl_xor_sync(0xffffffffu, rs_hi, 2);
            l_lo += rs_lo;  l_hi += rs_hi;
            // ---- O += P V (bf16x3), V^T tiles ----
#pragma unroll
            for (int pd = 0; pd < 4; pd++) {
#pragma unroll
                for (int kk = 0; kk < 4; kk++) {
                    u32 vh[4], vl[4];
                    LDSM4(vh, s + 2 * KTL * AROWB + (u32)pd * (16 * AROWB) + boff + kk * 32);
                    LDSM4(vl, s + 3 * KTL * AROWB + (u32)pd * (16 * AROWB) + boff + kk * 32);
                    MMA16816(o[2 * pd],     ph[kk], vh[0], vh[1]);
                    MMA16816(o[2 * pd],     pl[kk], vh[0], vh[1]);
                    MMA16816(o[2 * pd],     ph[kk], vl[0], vl[1]);
                    MMA16816(o[2 * pd + 1], ph[kk], vh[2], vh[3]);
                    MMA16816(o[2 * pd + 1], pl[kk], vh[2], vh[3]);
                    MMA16816(o[2 * pd + 1], ph[kk], vl[2], vl[3]);
                }
            }
        }
        __syncthreads();
    }

    // ---- epilogue: y (bf16 hi/lo) -> g_yh/g_yl [b,t,c] ----
    const float inv_lo = 1.f / l_lo;
    const float inv_hi = 1.f / l_hi;
    const int bb = bh >> 4, h = bh & 15;
    const int t_a = wrow0 + g;
#pragma unroll
    for (int nt = 0; nt < 8; nt++) {
        const int c = h * DD + nt * 8 + tg * 2;
        size_t i0 = ((size_t)bb * TT + t_a) * CCH + c;
        size_t i1 = ((size_t)bb * TT + t_a + 8) * CCH + c;
        u32 hi, lo;
        split2(o[nt][0] * inv_lo, o[nt][1] * inv_lo, hi, lo);
        *(u32*)(g_yh + i0) = hi;  *(u32*)(g_yl + i0) = lo;
        split2(o[nt][2] * inv_hi, o[nt][3] * inv_hi, hi, lo);
        *(u32*)(g_yh + i1) = hi;  *(u32*)(g_yl + i1) = lo;
    }
}

// ---------------------------------------------------------------------------
extern "C" void kernel_launch(void* const* d_in, const int* in_sizes, int n_in,
                              void* d_out, int out_size)
{
    const float* x      = (const float*)d_in[0];
    const float* w_qkv  = (const float*)d_in[1];
    const float* w_proj = (const float*)d_in[2];
    float* out          = (float*)d_out;

    cudaFuncSetAttribute(gemm_bf16s<1>, cudaFuncAttributeMaxDynamicSharedMemorySize, GSMEM);
    cudaFuncSetAttribute(gemm_bf16s<0>, cudaFuncAttributeMaxDynamicSharedMemorySize, GSMEM);
    cudaFuncSetAttribute(attn_tc, cudaFuncAttributeMaxDynamicSharedMemorySize, ASMEM);

    __nv_bfloat16 *xh, *xl, *yh, *yl, *wqh, *wql, *wph, *wpl;
    cudaGetSymbolAddress((void**)&xh,  g_xh);
    cudaGetSymbolAddress((void**)&xl,  g_xl);
    cudaGetSymbolAddress((void**)&yh,  g_yh);
    cudaGetSymbolAddress((void**)&yl,  g_yl);
    cudaGetSymbolAddress((void**)&wqh, g_wqh);
    cudaGetSymbolAddress((void**)&wql, g_wql);
    cudaGetSymbolAddress((void**)&wph, g_wph);
    cudaGetSymbolAddress((void**)&wpl, g_wpl);

    // 0) operand prep
    transpose_split<<<dim3(3 * CCH / 32, KDIM / 32), 256>>>(w_qkv, wqh, wql, 3 * CCH);
    transpose_split<<<dim3(CCH / 32, KDIM / 32), 256>>>(w_proj, wph, wpl, CCH);
    split_kernel<<<(MM * KDIM / 4 + 255) / 256, 256>>>(x, xh, xl, MM * KDIM / 4);

    // 1) QKV GEMM -> bf16 hi/lo q,k,v in [b,h,t,d]
    gemm_bf16s<1><<<dim3(3 * CCH / 128, MM / 128), 256, GSMEM>>>(xh, xl, wqh, wql, nullptr, 3 * CCH);

    // 2) V transpose -> [b,h,d,t]
    vt_kernel<<<dim3(TT / 64, BHN), 256>>>();

    // 3) tensor-core causal flash attention -> g_yh/g_yl
    attn_tc<<<dim3(TT / 128, BHN), 256, ASMEM>>>();

    // 4) output projection
    gemm_bf16s<0><<<dim3(CCH / 128, MM / 128), 256, GSMEM>>>(yh, yl, wph, wpl, out, CCH);
}

// round 9
// speedup vs baseline: 3.1742x; 1.0899x over previous
#include <cuda_runtime.h>
#include <cuda_bf16.h>

typedef unsigned int u32;
typedef unsigned long long u64;
typedef unsigned short u16;

#define TT 2048
#define DD 64
#define CCH 1024
#define HH 16
#define BB 4
#define BHN (BB*HH)
#define MM (BB*TT)
#define KDIM 1024

// ------------------------- scratch (device globals) -------------------------
__device__ __align__(1024) __nv_bfloat16 g_xh[(size_t)MM * KDIM];
__device__ __align__(1024) __nv_bfloat16 g_xl[(size_t)MM * KDIM];
__device__ __align__(1024) __nv_bfloat16 g_wqh[(size_t)3 * CCH * KDIM];
__device__ __align__(1024) __nv_bfloat16 g_wql[(size_t)3 * CCH * KDIM];
__device__ __align__(1024) __nv_bfloat16 g_wph[(size_t)CCH * KDIM];
__device__ __align__(1024) __nv_bfloat16 g_wpl[(size_t)CCH * KDIM];

__device__ __align__(1024) __nv_bfloat16 g_qh[(size_t)BHN * TT * DD];  // [b,h,t,d]
__device__ __align__(1024) __nv_bfloat16 g_ql[(size_t)BHN * TT * DD];
__device__ __align__(1024) __nv_bfloat16 g_kh[(size_t)BHN * TT * DD];
__device__ __align__(1024) __nv_bfloat16 g_kl[(size_t)BHN * TT * DD];
__device__ __align__(1024) __nv_bfloat16 g_vh[(size_t)BHN * TT * DD];
__device__ __align__(1024) __nv_bfloat16 g_vl[(size_t)BHN * TT * DD];
__device__ __align__(1024) __nv_bfloat16 g_vth[(size_t)BHN * DD * TT]; // [b,h,d,t]
__device__ __align__(1024) __nv_bfloat16 g_vtl[(size_t)BHN * DD * TT];
__device__ __align__(1024) __nv_bfloat16 g_yh[(size_t)MM * CCH];       // [b,t,c]
__device__ __align__(1024) __nv_bfloat16 g_yl[(size_t)MM * CCH];

// ------------------------- PTX helpers -------------------------
__device__ __forceinline__ u32 smem_u32(const void* p) {
    u32 a;
    asm("{ .reg .u64 t; cvta.to.shared.u64 t, %1; cvt.u32.u64 %0, t; }" : "=r"(a) : "l"(p));
    return a;
}

#define CP_ASYNC16(dst, src) \
    asm volatile("cp.async.cg.shared.global [%0], [%1], 16;" :: "r"(dst), "l"(src) : "memory")
#define CP_COMMIT() asm volatile("cp.async.commit_group;" ::: "memory")
#define CP_WAIT(n)  asm volatile("cp.async.wait_group %0;" :: "n"(n) : "memory")

#define LDSM4(r, addr) \
    asm volatile("ldmatrix.sync.aligned.m8n8.x4.shared.b16 {%0,%1,%2,%3}, [%4];" \
        : "=r"((r)[0]), "=r"((r)[1]), "=r"((r)[2]), "=r"((r)[3]) : "r"(addr))

#define MMA16816(d, a, b0, b1) \
    asm volatile("mma.sync.aligned.m16n8k16.row.col.f32.bf16.bf16.f32 " \
        "{%0,%1,%2,%3}, {%4,%5,%6,%7}, {%8,%9}, {%0,%1,%2,%3};" \
        : "+f"((d)[0]), "+f"((d)[1]), "+f"((d)[2]), "+f"((d)[3]) \
        : "r"((a)[0]), "r"((a)[1]), "r"((a)[2]), "r"((a)[3]), "r"(b0), "r"(b1))

__device__ __forceinline__ u32 pack2bf(__nv_bfloat16 lo, __nv_bfloat16 hi) {
    return (u32)*(u16*)&lo | ((u32)*(u16*)&hi << 16);
}
// split two f32 into packed bf16 hi-pair and lo-pair
__device__ __forceinline__ void split2(float a, float b, u32& hi, u32& lo) {
    __nv_bfloat16 ha = __float2bfloat16_rn(a), hb = __float2bfloat16_rn(b);
    __nv_bfloat16 la = __float2bfloat16_rn(a - __bfloat162float(ha));
    __nv_bfloat16 lb = __float2bfloat16_rn(b - __bfloat162float(hb));
    hi = pack2bf(ha, hb);
    lo = pack2bf(la, lb);
}

// ------------------------- fp32 -> bf16 hi/lo split (x only) -------------------------
__global__ void __launch_bounds__(256) split_kernel(const float* __restrict__ src,
                                                    __nv_bfloat16* __restrict__ hi,
                                                    __nv_bfloat16* __restrict__ lo, int n4)
{
    int i = blockIdx.x * 256 + threadIdx.x;
    if (i >= n4) return;
    float4 v = ((const float4*)src)[i];
    u32 h0, l0, h1, l1;
    split2(v.x, v.y, h0, l0);
    split2(v.z, v.w, h1, l1);
    ((uint2*)hi)[i] = make_uint2(h0, h1);
    ((uint2*)lo)[i] = make_uint2(l0, l1);
}

// ------------------------- weight transpose + split -------------------------
__global__ void __launch_bounds__(256) transpose_split(const float* __restrict__ W,
                                                       __nv_bfloat16* __restrict__ dh,
                                                       __nv_bfloat16* __restrict__ dl, int Ndim)
{
    __shared__ float tile[32][33];
    const int n0 = blockIdx.x * 32;
    const int k0 = blockIdx.y * 32;
    const int tx = threadIdx.x & 31;
    const int ty = threadIdx.x >> 5;
#pragma unroll
    for (int r = 0; r < 4; r++)
        tile[ty + 8 * r][tx] = W[(size_t)(k0 + ty + 8 * r) * Ndim + n0 + tx];
    __syncthreads();
#pragma unroll
    for (int r = 0; r < 4; r++) {
        float v = tile[tx][ty + 8 * r];
        __nv_bfloat16 h = __float2bfloat16_rn(v);
        __nv_bfloat16 l = __float2bfloat16_rn(v - __bfloat162float(h));
        size_t idx = (size_t)(n0 + ty + 8 * r) * KDIM + k0 + tx;
        dh[idx] = h;
        dl[idx] = l;
    }
}

// ------------------------- V transpose: [b,h,t,d] -> [b,h,d,t] (bf16 hi+lo) -----------
__global__ void __launch_bounds__(256) vt_kernel()
{
    __shared__ __nv_bfloat16 sh[64][72];
    __shared__ __nv_bfloat16 sl[64][72];
    const int bh = blockIdx.y;
    const int t0 = blockIdx.x * 64;
    const int tid = threadIdx.x;
#pragma unroll
    for (int k = 0; k < 4; k++) {
        int ch = tid + k * 256;
        int hl = ch >> 9, rem = ch & 511;
        int row = rem >> 3, c = rem & 7;
        uint4 v = *(const uint4*)((hl ? g_vl : g_vh) + ((size_t)bh * TT + t0 + row) * DD + c * 8);
        __nv_bfloat16* dst = hl ? &sl[row][c * 8] : &sh[row][c * 8];
        *(uint4*)dst = v;
    }
    __syncthreads();
#pragma unroll
    for (int k = 0; k < 4; k++) {
        int ch = tid + k * 256;
        int hl = ch >> 9, rem = ch & 511;
        int d = rem >> 3, c = rem & 7;
        u32 w[4];
#pragma unroll
        for (int e = 0; e < 4; e++) {
            __nv_bfloat16 a = hl ? sl[c * 8 + 2 * e][d]     : sh[c * 8 + 2 * e][d];
            __nv_bfloat16 b = hl ? sl[c * 8 + 2 * e + 1][d] : sh[c * 8 + 2 * e + 1][d];
            w[e] = pack2bf(a, b);
        }
        __nv_bfloat16* dst = (hl ? g_vtl : g_vth) + ((size_t)bh * DD + d) * TT + t0 + c * 8;
        *(uint4*)dst = make_uint4(w[0], w[1], w[2], w[3]);
    }
}

// ------------------------- bf16-split tensor-core GEMM -------------------------
#define BK 32
#define NCH (KDIM / BK)
#define ROWB 80
#define TILEB (128 * ROWB)
#define STAGEB (4 * TILEB)
#define GSMEM (2 * STAGEB)

template <int EPI>   // 1: split-scatter to g_{q,k,v}{h,l}; 0: fp32 store to C
__global__ void __launch_bounds__(256, 2) gemm_bf16s(
    const __nv_bfloat16* __restrict__ Ah, const __nv_bfloat16* __restrict__ Al,
    const __nv_bfloat16* __restrict__ Bh, const __nv_bfloat16* __restrict__ Bl,
    float* __restrict__ C, int Nout)
{
    extern __shared__ char smem[];
    const u32 sb   = smem_u32(smem);
    const int tid  = threadIdx.x;
    const int lane = tid & 31;
    const int wid  = tid >> 5;
    const int wm   = wid & 3;
    const int wn   = wid >> 2;
    const int m0   = blockIdx.y * 128;
    const int n0   = blockIdx.x * 128;

    auto load_stage = [&](int kc, int stage) {
        const int k0 = kc * BK;
        const u32 s = sb + stage * STAGEB;
#pragma unroll
        for (int r = 0; r < 2; r++) {
            int ch  = tid + r * 256;
            int row = ch >> 2;
            int c4  = ch & 3;
            u32 dst = (u32)(row * ROWB + c4 * 16);
            size_t asrc = (size_t)(m0 + row) * KDIM + k0 + c4 * 8;
            size_t bsrc = (size_t)(n0 + row) * KDIM + k0 + c4 * 8;
            CP_ASYNC16(s + dst,              Ah + asrc);
            CP_ASYNC16(s + TILEB + dst,      Al + asrc);
            CP_ASYNC16(s + 2 * TILEB + dst,  Bh + bsrc);
            CP_ASYNC16(s + 3 * TILEB + dst,  Bl + bsrc);
        }
    };

    const u32 a_off = (u32)((lane & 15) * ROWB + ((lane >> 4) << 4));
    const u32 b_off = (u32)(((((lane >> 4) << 3) + (lane & 7)) * ROWB) + (((lane >> 3) & 1) << 4));

    float acc[2][8][4];
#pragma unroll
    for (int mt = 0; mt < 2; mt++)
#pragma unroll
        for (int nt = 0; nt < 8; nt++)
#pragma unroll
            for (int q = 0; q < 4; q++) acc[mt][nt][q] = 0.f;

    load_stage(0, 0);
    CP_COMMIT();

    for (int i = 0; i < NCH; i++) {
        if (i + 1 < NCH) { load_stage(i + 1, (i + 1) & 1); CP_COMMIT(); CP_WAIT(1); }
        else             { CP_WAIT(0); }
        __syncthreads();

        const u32 s  = sb + (i & 1) * STAGEB;
        const u32 aH = s             + (u32)(wm * 32) * ROWB + a_off;
        const u32 aL = s + TILEB     + (u32)(wm * 32) * ROWB + a_off;
        const u32 bH = s + 2 * TILEB + (u32)(wn * 64) * ROWB + b_off;
        const u32 bL = s + 3 * TILEB + (u32)(wn * 64) * ROWB + b_off;

#pragma unroll
        for (int kt = 0; kt < 2; kt++) {
            const u32 ktb = (u32)kt * 32;
            u32 ah[2][4], al[2][4];
#pragma unroll
            for (int mt = 0; mt < 2; mt++) {
                LDSM4(ah[mt], aH + (u32)mt * (16 * ROWB) + ktb);
                LDSM4(al[mt], aL + (u32)mt * (16 * ROWB) + ktb);
            }
            u32 bh[4][4], bl[4][4];
#pragma unroll
            for (int p = 0; p < 4; p++) {
                LDSM4(bh[p], bH + (u32)p * (16 * ROWB) + ktb);
                LDSM4(bl[p], bL + (u32)p * (16 * ROWB) + ktb);
            }
#pragma unroll
            for (int mt = 0; mt < 2; mt++)
#pragma unroll
                for (int nt = 0; nt < 8; nt++) {
                    const int p = nt >> 1, e = (nt & 1) * 2;
                    MMA16816(acc[mt][nt], ah[mt], bh[p][e], bh[p][e + 1]);
                    MMA16816(acc[mt][nt], ah[mt], bl[p][e], bl[p][e + 1]);
                    MMA16816(acc[mt][nt], al[mt], bh[p][e], bh[p][e + 1]);
                }
        }
        __syncthreads();
    }

    // epilogue: one fragment at a time to keep live temporaries minimal
#pragma unroll
    for (int mt = 0; mt < 2; mt++) {
        const int r0 = m0 + wm * 32 + mt * 16 + (lane >> 2);
#pragma unroll
        for (int nt = 0; nt < 8; nt++) {
            const int n = n0 + wn * 64 + nt * 8 + (lane & 3) * 2;
            if (EPI == 0) {
                float* p0 = C + (size_t)r0 * Nout + n;
                float* p1 = C + (size_t)(r0 + 8) * Nout + n;
                *(float2*)p0 = make_float2(acc[mt][nt][0], acc[mt][nt][1]);
                *(float2*)p1 = make_float2(acc[mt][nt][2], acc[mt][nt][3]);
            } else {
                const int sec = n >> 10;
                const int cc  = n & 1023;
                const int h   = cc >> 6, dd = cc & 63;
                __nv_bfloat16* bhp = (sec == 0) ? g_qh : (sec == 1) ? g_kh : g_vh;
                __nv_bfloat16* blp = (sec == 0) ? g_ql : (sec == 1) ? g_kl : g_vl;
                {
                    const int bb0 = r0 >> 11, tt0 = r0 & 2047;
                    size_t i0 = ((size_t)(bb0 * HH + h) * TT + tt0) * DD + dd;
                    u32 hi, lo;
                    split2(acc[mt][nt][0], acc[mt][nt][1], hi, lo);
                    *(u32*)(bhp + i0) = hi;  *(u32*)(blp + i0) = lo;
                }
                {
                    const int r1 = r0 + 8;
                    const int bb1 = r1 >> 11, tt1 = r1 & 2047;
                    size_t i1 = ((size_t)(bb1 * HH + h) * TT + tt1) * DD + dd;
                    u32 hi, lo;
                    split2(acc[mt][nt][2], acc[mt][nt][3], hi, lo);
                    *(u32*)(bhp + i1) = hi;  *(u32*)(blp + i1) = lo;
                }
            }
        }
    }
}

// ------------------------- tensor-core flash attention -------------------------
#define AROW 72
#define AROWB 144
#define KTL 64
#define ASTG (4 * KTL * AROWB)
#define ASMEM (2 * ASTG)

__global__ void __launch_bounds__(256, 1) attn_tc()
{
    extern __shared__ char smem[];
    const u32 sb   = smem_u32(smem);
    const int tid  = threadIdx.x;
    const int lane = tid & 31;
    const int wid  = tid >> 5;
    const int qi   = (int)gridDim.x - 1 - (int)blockIdx.x;
    const int bh   = blockIdx.y;
    const int q0   = qi * 128;
    const int g    = lane >> 2, tg = lane & 3;
    const int wrow0 = q0 + wid * 16;

#pragma unroll
    for (int r = 0; r < 8; r++) {
        int ch  = tid + r * 256;
        int hl  = ch >> 10;
        int rem = ch & 1023;
        int row = rem >> 3, c = rem & 7;
        const __nv_bfloat16* src = (hl ? g_ql : g_qh) + ((size_t)bh * TT + q0 + row) * DD + c * 8;
        CP_ASYNC16(sb + hl * (128 * AROWB) + row * AROWB + c * 16, src);
    }
    CP_COMMIT();

    auto load_kv = [&](int kt, int buf) {
        const int j0 = kt * KTL;
        const u32 s = sb + buf * ASTG;
#pragma unroll
        for (int r = 0; r < 8; r++) {
            int ch  = tid + r * 256;
            int mat = ch >> 9;
            int rem = ch & 511;
            int row = rem >> 3, c = rem & 7;
            const __nv_bfloat16* src;
            if      (mat == 0) src = g_kh  + ((size_t)bh * TT + j0 + row) * DD + c * 8;
            else if (mat == 1) src = g_kl  + ((size_t)bh * TT + j0 + row) * DD + c * 8;
            else if (mat == 2) src = g_vth + ((size_t)bh * DD + row) * TT + j0 + c * 8;
            else               src = g_vtl + ((size_t)bh * DD + row) * TT + j0 + c * 8;
            CP_ASYNC16(s + mat * (KTL * AROWB) + row * AROWB + c * 16, src);
        }
        CP_COMMIT();
    };

    load_kv(0, 1);
    CP_WAIT(1);
    __syncthreads();

    u32 qh[4][4], ql[4][4];
    {
        const u32 qb = sb + (u32)(wid * 16 + (lane & 15)) * AROWB + ((lane >> 4) << 4);
#pragma unroll
        for (int ks = 0; ks < 4; ks++) {
            LDSM4(qh[ks], qb + ks * 32);
            LDSM4(ql[ks], qb + 128 * AROWB + ks * 32);
        }
    }
    __syncthreads();

    float o[8][4];
#pragma unroll
    for (int nt = 0; nt < 8; nt++)
#pragma unroll
        for (int e = 0; e < 4; e++) o[nt][e] = 0.f;
    float m_lo = -1e30f, m_hi = -1e30f, l_lo = 0.f, l_hi = 0.f;

    const u32 boff = (u32)((((lane >> 4) << 3) + (lane & 7)) * AROWB + (((lane >> 3) & 1) << 4));
    const int nkt = 2 * qi + 2;

    for (int kt = 0; kt < nkt; kt++) {
        if (kt + 1 < nkt) { load_kv(kt + 1, kt & 1); CP_WAIT(1); }
        else              { CP_WAIT(0); }
        __syncthreads();

        const u32 s  = sb + ((kt + 1) & 1) * ASTG;
        const int j0 = kt * KTL;

        if (j0 <= wrow0 + 15) {
            float sacc[8][4];
#pragma unroll
            for (int nt = 0; nt < 8; nt++)
#pragma unroll
                for (int e = 0; e < 4; e++) sacc[nt][e] = 0.f;
#pragma unroll
            for (int p = 0; p < 4; p++) {
#pragma unroll
                for (int ks = 0; ks < 4; ks++) {
                    u32 kh[4], kl[4];
                    LDSM4(kh, s + (u32)p * (16 * AROWB) + boff + ks * 32);
                    LDSM4(kl, s + KTL * AROWB + (u32)p * (16 * AROWB) + boff + ks * 32);
                    MMA16816(sacc[2 * p],     qh[ks], kh[0], kh[1]);
                    MMA16816(sacc[2 * p],     ql[ks], kh[0], kh[1]);
                    MMA16816(sacc[2 * p],     qh[ks], kl[0], kl[1]);
                    MMA16816(sacc[2 * p + 1], qh[ks], kh[2], kh[3]);
                    MMA16816(sacc[2 * p + 1], ql[ks], kh[2], kh[3]);
                    MMA16816(sacc[2 * p + 1], qh[ks], kl[2], kl[3]);
                }
            }
            const int row_a = wrow0 + g;
            const bool diag = (j0 + 63 > wrow0);
            float tmax_lo = -1e30f, tmax_hi = -1e30f;
#pragma unroll
            for (int nt = 0; nt < 8; nt++) {
#pragma unroll
                for (int e = 0; e < 2; e++) {
                    int j = j0 + nt * 8 + tg * 2 + e;
                    float v0 = sacc[nt][e]     * 0.125f;
                    float v1 = sacc[nt][e + 2] * 0.125f;
                    if (diag) {
                        if (j > row_a)     v0 = -1e30f;
                        if (j > row_a + 8) v1 = -1e30f;
                    }
                    sacc[nt][e]     = v0;
                    sacc[nt][e + 2] = v1;
                    tmax_lo = fmaxf(tmax_lo, v0);
                    tmax_hi = fmaxf(tmax_hi, v1);
                }
            }
            tmax_lo = fmaxf(tmax_lo, __shfl_xor_sync(0xffffffffu, tmax_lo, 1));
            tmax_lo = fmaxf(tmax_lo, __shfl_xor_sync(0xffffffffu, tmax_lo, 2));
            tmax_hi = fmaxf(tmax_hi, __shfl_xor_sync(0xffffffffu, tmax_hi, 1));
            tmax_hi = fmaxf(tmax_hi, __shfl_xor_sync(0xffffffffu, tmax_hi, 2));

            float mn_lo = fmaxf(m_lo, tmax_lo);
            float mn_hi = fmaxf(m_hi, tmax_hi);
            float c_lo = __expf(m_lo - mn_lo);
            float c_hi = __expf(m_hi - mn_hi);
            m_lo = mn_lo; m_hi = mn_hi;
            l_lo *= c_lo; l_hi *= c_hi;
#pragma unroll
            for (int nt = 0; nt < 8; nt++) {
                o[nt][0] *= c_lo; o[nt][1] *= c_lo;
                o[nt][2] *= c_hi; o[nt][3] *= c_hi;
            }
            u32 ph[4][4], pl[4][4];
            float rs_lo = 0.f, rs_hi = 0.f;
#pragma unroll
            for (int kk = 0; kk < 4; kk++) {
#pragma unroll
                for (int half = 0; half < 2; half++) {
                    const int t2 = 2 * kk + half;
                    float p0 = __expf(sacc[t2][0] - m_lo);
                    float p1 = __expf(sacc[t2][1] - m_lo);
                    float p2 = __expf(sacc[t2][2] - m_hi);
                    float p3 = __expf(sacc[t2][3] - m_hi);
                    rs_lo += p0 + p1;  rs_hi += p2 + p3;
                    split2(p0, p1, ph[kk][2 * half],     pl[kk][2 * half]);
                    split2(p2, p3, ph[kk][2 * half + 1], pl[kk][2 * half + 1]);
                }
            }
            rs_lo += __shfl_xor_sync(0xffffffffu, rs_lo, 1);
            rs_lo += __shfl_xor_sync(0xffffffffu, rs_lo, 2);
            rs_hi += __shfl_xor_sync(0xffffffffu, rs_hi, 1);
            rs_hi += __shfl_xor_sync(0xffffffffu, rs_hi, 2);
            l_lo += rs_lo;  l_hi += rs_hi;
#pragma unroll
            for (int pd = 0; pd < 4; pd++) {
#pragma unroll
                for (int kk = 0; kk < 4; kk++) {
                    u32 vh[4], vl[4];
                    LDSM4(vh, s + 2 * KTL * AROWB + (u32)pd * (16 * AROWB) + boff + kk * 32);
                    LDSM4(vl, s + 3 * KTL * AROWB + (u32)pd * (16 * AROWB) + boff + kk * 32);
                    MMA16816(o[2 * pd],     ph[kk], vh[0], vh[1]);
                    MMA16816(o[2 * pd],     pl[kk], vh[0], vh[1]);
                    MMA16816(o[2 * pd],     ph[kk], vl[0], vl[1]);
                    MMA16816(o[2 * pd + 1], ph[kk], vh[2], vh[3]);
                    MMA16816(o[2 * pd + 1], pl[kk], vh[2], vh[3]);
                    MMA16816(o[2 * pd + 1], ph[kk], vl[2], vl[3]);
                }
            }
        }
        __syncthreads();
    }

    const float inv_lo = 1.f / l_lo;
    const float inv_hi = 1.f / l_hi;
    const int bb = bh >> 4, h = bh & 15;
    const int t_a = wrow0 + g;
#pragma unroll
    for (int nt = 0; nt < 8; nt++) {
        const int c = h * DD + nt * 8 + tg * 2;
        size_t i0 = ((size_t)bb * TT + t_a) * CCH + c;
        size_t i1 = ((size_t)bb * TT + t_a + 8) * CCH + c;
        u32 hi, lo;
        split2(o[nt][0] * inv_lo, o[nt][1] * inv_lo, hi, lo);
        *(u32*)(g_yh + i0) = hi;  *(u32*)(g_yl + i0) = lo;
        split2(o[nt][2] * inv_hi, o[nt][3] * inv_hi, hi, lo);
        *(u32*)(g_yh + i1) = hi;  *(u32*)(g_yl + i1) = lo;
    }
}

// ---------------------------------------------------------------------------
extern "C" void kernel_launch(void* const* d_in, const int* in_sizes, int n_in,
                              void* d_out, int out_size)
{
    const float* x      = (const float*)d_in[0];
    const float* w_qkv  = (const float*)d_in[1];
    const float* w_proj = (const float*)d_in[2];
    float* out          = (float*)d_out;

    cudaFuncSetAttribute(gemm_bf16s<1>, cudaFuncAttributeMaxDynamicSharedMemorySize, GSMEM);
    cudaFuncSetAttribute(gemm_bf16s<0>, cudaFuncAttributeMaxDynamicSharedMemorySize, GSMEM);
    cudaFuncSetAttribute(attn_tc, cudaFuncAttributeMaxDynamicSharedMemorySize, ASMEM);

    __nv_bfloat16 *xh, *xl, *yh, *yl, *wqh, *wql, *wph, *wpl;
    cudaGetSymbolAddress((void**)&xh,  g_xh);
    cudaGetSymbolAddress((void**)&xl,  g_xl);
    cudaGetSymbolAddress((void**)&yh,  g_yh);
    cudaGetSymbolAddress((void**)&yl,  g_yl);
    cudaGetSymbolAddress((void**)&wqh, g_wqh);
    cudaGetSymbolAddress((void**)&wql, g_wql);
    cudaGetSymbolAddress((void**)&wph, g_wph);
    cudaGetSymbolAddress((void**)&wpl, g_wpl);

    // 0) operand prep
    transpose_split<<<dim3(3 * CCH / 32, KDIM / 32), 256>>>(w_qkv, wqh, wql, 3 * CCH);
    transpose_split<<<dim3(CCH / 32, KDIM / 32), 256>>>(w_proj, wph, wpl, CCH);
    split_kernel<<<(MM * KDIM / 4 + 255) / 256, 256>>>(x, xh, xl, MM * KDIM / 4);

    // 1) QKV GEMM -> bf16 hi/lo q,k,v in [b,h,t,d]
    gemm_bf16s<1><<<dim3(3 * CCH / 128, MM / 128), 256, GSMEM>>>(xh, xl, wqh, wql, nullptr, 3 * CCH);

    // 2) V transpose -> [b,h,d,t]
    vt_kernel<<<dim3(TT / 64, BHN), 256>>>();

    // 3) tensor-core causal flash attention -> g_yh/g_yl
    attn_tc<<<dim3(TT / 128, BHN), 256, ASMEM>>>();

    // 4) output projection
    gemm_bf16s<0><<<dim3(CCH / 128, MM / 128), 256, GSMEM>>>(yh, yl, wph, wpl, out, CCH);
}

// round 11
// speedup vs baseline: 3.4573x; 1.0892x over previous
#include <cuda_runtime.h>
#include <cuda_bf16.h>

typedef unsigned int u32;
typedef unsigned long long u64;
typedef unsigned short u16;

#define TT 2048
#define DD 64
#define CCH 1024
#define HH 16
#define BB 4
#define BHN (BB*HH)
#define MM (BB*TT)
#define KDIM 1024

// ------------------------- scratch (device globals) -------------------------
__device__ __align__(1024) __nv_bfloat16 g_xh[(size_t)MM * KDIM];
__device__ __align__(1024) __nv_bfloat16 g_xl[(size_t)MM * KDIM];
__device__ __align__(1024) __nv_bfloat16 g_wqh[(size_t)3 * CCH * KDIM];
__device__ __align__(1024) __nv_bfloat16 g_wql[(size_t)3 * CCH * KDIM];
__device__ __align__(1024) __nv_bfloat16 g_wph[(size_t)CCH * KDIM];
__device__ __align__(1024) __nv_bfloat16 g_wpl[(size_t)CCH * KDIM];

__device__ __align__(1024) __nv_bfloat16 g_qh[(size_t)BHN * TT * DD];  // [b,h,t,d]
__device__ __align__(1024) __nv_bfloat16 g_ql[(size_t)BHN * TT * DD];
__device__ __align__(1024) __nv_bfloat16 g_kh[(size_t)BHN * TT * DD];
__device__ __align__(1024) __nv_bfloat16 g_kl[(size_t)BHN * TT * DD];
__device__ __align__(1024) __nv_bfloat16 g_vh[(size_t)BHN * TT * DD];
__device__ __align__(1024) __nv_bfloat16 g_vl[(size_t)BHN * TT * DD];
__device__ __align__(1024) __nv_bfloat16 g_vth[(size_t)BHN * DD * TT]; // [b,h,d,t]
__device__ __align__(1024) __nv_bfloat16 g_vtl[(size_t)BHN * DD * TT];
__device__ __align__(1024) __nv_bfloat16 g_yh[(size_t)MM * CCH];       // [b,t,c]
__device__ __align__(1024) __nv_bfloat16 g_yl[(size_t)MM * CCH];

// ------------------------- PTX helpers -------------------------
__device__ __forceinline__ u32 smem_u32(const void* p) {
    u32 a;
    asm("{ .reg .u64 t; cvta.to.shared.u64 t, %1; cvt.u32.u64 %0, t; }" : "=r"(a) : "l"(p));
    return a;
}

#define CP_ASYNC16(dst, src) \
    asm volatile("cp.async.cg.shared.global [%0], [%1], 16;" :: "r"(dst), "l"(src) : "memory")
#define CP_COMMIT() asm volatile("cp.async.commit_group;" ::: "memory")
#define CP_WAIT(n)  asm volatile("cp.async.wait_group %0;" :: "n"(n) : "memory")

#define LDSM4(r, addr) \
    asm volatile("ldmatrix.sync.aligned.m8n8.x4.shared.b16 {%0,%1,%2,%3}, [%4];" \
        : "=r"((r)[0]), "=r"((r)[1]), "=r"((r)[2]), "=r"((r)[3]) : "r"(addr))

#define MMA16816(d, a, b0, b1) \
    asm volatile("mma.sync.aligned.m16n8k16.row.col.f32.bf16.bf16.f32 " \
        "{%0,%1,%2,%3}, {%4,%5,%6,%7}, {%8,%9}, {%0,%1,%2,%3};" \
        : "+f"((d)[0]), "+f"((d)[1]), "+f"((d)[2]), "+f"((d)[3]) \
        : "r"((a)[0]), "r"((a)[1]), "r"((a)[2]), "r"((a)[3]), "r"(b0), "r"(b1))

__device__ __forceinline__ u32 pack2bf(__nv_bfloat16 lo, __nv_bfloat16 hi) {
    return (u32)*(u16*)&lo | ((u32)*(u16*)&hi << 16);
}
__device__ __forceinline__ void split2(float a, float b, u32& hi, u32& lo) {
    __nv_bfloat16 ha = __float2bfloat16_rn(a), hb = __float2bfloat16_rn(b);
    __nv_bfloat16 la = __float2bfloat16_rn(a - __bfloat162float(ha));
    __nv_bfloat16 lb = __float2bfloat16_rn(b - __bfloat162float(hb));
    hi = pack2bf(ha, hb);
    lo = pack2bf(la, lb);
}

// ------------------------- fp32 -> bf16 hi/lo split -------------------------
__global__ void __launch_bounds__(256) split_kernel(const float* __restrict__ src,
                                                    __nv_bfloat16* __restrict__ hi,
                                                    __nv_bfloat16* __restrict__ lo, int n4)
{
    int i = blockIdx.x * 256 + threadIdx.x;
    if (i >= n4) return;
    float4 v = ((const float4*)src)[i];
    u32 h0, l0, h1, l1;
    split2(v.x, v.y, h0, l0);
    split2(v.z, v.w, h1, l1);
    ((uint2*)hi)[i] = make_uint2(h0, h1);
    ((uint2*)lo)[i] = make_uint2(l0, l1);
}

// ------------------------- weight transpose + split -------------------------
__global__ void __launch_bounds__(256) transpose_split(const float* __restrict__ W,
                                                       __nv_bfloat16* __restrict__ dh,
                                                       __nv_bfloat16* __restrict__ dl, int Ndim)
{
    __shared__ float tile[32][33];
    const int n0 = blockIdx.x * 32;
    const int k0 = blockIdx.y * 32;
    const int tx = threadIdx.x & 31;
    const int ty = threadIdx.x >> 5;
#pragma unroll
    for (int r = 0; r < 4; r++)
        tile[ty + 8 * r][tx] = W[(size_t)(k0 + ty + 8 * r) * Ndim + n0 + tx];
    __syncthreads();
#pragma unroll
    for (int r = 0; r < 4; r++) {
        float v = tile[tx][ty + 8 * r];
        __nv_bfloat16 h = __float2bfloat16_rn(v);
        __nv_bfloat16 l = __float2bfloat16_rn(v - __bfloat162float(h));
        size_t idx = (size_t)(n0 + ty + 8 * r) * KDIM + k0 + tx;
        dh[idx] = h;
        dl[idx] = l;
    }
}

// ------------------------- V transpose: [b,h,t,d] -> [b,h,d,t] -------------------------
__global__ void __launch_bounds__(256) vt_kernel()
{
    __shared__ __nv_bfloat16 sh[64][72];
    __shared__ __nv_bfloat16 sl[64][72];
    const int bh = blockIdx.y;
    const int t0 = blockIdx.x * 64;
    const int tid = threadIdx.x;
#pragma unroll
    for (int k = 0; k < 4; k++) {
        int ch = tid + k * 256;
        int hl = ch >> 9, rem = ch & 511;
        int row = rem >> 3, c = rem & 7;
        uint4 v = *(const uint4*)((hl ? g_vl : g_vh) + ((size_t)bh * TT + t0 + row) * DD + c * 8);
        __nv_bfloat16* dst = hl ? &sl[row][c * 8] : &sh[row][c * 8];
        *(uint4*)dst = v;
    }
    __syncthreads();
#pragma unroll
    for (int k = 0; k < 4; k++) {
        int ch = tid + k * 256;
        int hl = ch >> 9, rem = ch & 511;
        int d = rem >> 3, c = rem & 7;
        u32 w[4];
#pragma unroll
        for (int e = 0; e < 4; e++) {
            __nv_bfloat16 a = hl ? sl[c * 8 + 2 * e][d]     : sh[c * 8 + 2 * e][d];
            __nv_bfloat16 b = hl ? sl[c * 8 + 2 * e + 1][d] : sh[c * 8 + 2 * e + 1][d];
            w[e] = pack2bf(a, b);
        }
        __nv_bfloat16* dst = (hl ? g_vtl : g_vth) + ((size_t)bh * DD + d) * TT + t0 + c * 8;
        *(uint4*)dst = make_uint4(w[0], w[1], w[2], w[3]);
    }
}

// ------------- bf16-split tensor-core GEMM (3-stage, swizzled 64B rows) -------------
// Layout: 64B rows, physical 16B-chunk = logical chunk ^ ((row>>1)&3)  (XOR bits 4-5).
#define BK 32
#define NCH (KDIM / BK)
#define TILEB (128 * 64)            // 8192
#define STAGEB (4 * TILEB)          // 32768: Ah, Al, Bh, Bl
#define GSMEM (3 * STAGEB + 128)    // 98432 (128B alignment slack)

template <int EPI>   // 1: split-scatter to g_{q,k,v}{h,l}; 0: fp32 store to C
__global__ void __launch_bounds__(256, 2) gemm_bf16s(
    const __nv_bfloat16* __restrict__ Ah, const __nv_bfloat16* __restrict__ Al,
    const __nv_bfloat16* __restrict__ Bh, const __nv_bfloat16* __restrict__ Bl,
    float* __restrict__ C, int Nout)
{
    extern __shared__ char smem[];
    const u32 sb   = (smem_u32(smem) + 127u) & ~127u;   // bits 4-5 clean
    const int tid  = threadIdx.x;
    const int lane = tid & 31;
    const int wid  = tid >> 5;
    const int wm   = wid & 3;
    const int wn   = wid >> 2;
    const int m0   = blockIdx.y * 128;
    const int n0   = blockIdx.x * 128;

    auto load_stage = [&](int kc, int stage) {
        const int k0 = kc * BK;
        const u32 s = sb + (u32)stage * STAGEB;
#pragma unroll
        for (int r = 0; r < 2; r++) {
            int ch  = tid + r * 256;
            int row = ch >> 2;
            int c4  = ch & 3;
            u32 dst = ((u32)(row * 64 + c4 * 16)) ^ ((u32)((row >> 1) & 3) << 4);
            size_t asrc = (size_t)(m0 + row) * KDIM + k0 + c4 * 8;
            size_t bsrc = (size_t)(n0 + row) * KDIM + k0 + c4 * 8;
            CP_ASYNC16(s + dst,              Ah + asrc);
            CP_ASYNC16(s + TILEB + dst,      Al + asrc);
            CP_ASYNC16(s + 2 * TILEB + dst,  Bh + bsrc);
            CP_ASYNC16(s + 3 * TILEB + dst,  Bl + bsrc);
        }
    };

    // per-lane constants (XOR terms are mt/p/kt-invariant: f has period 8, offsets mult of 16)
    const u32 a_row64 = (u32)(wm * 32 + (lane & 15)) * 64;
    const u32 cA16    = (u32)((lane >> 4) << 4);
    const u32 xA      = (u32)((((lane & 15) >> 1) & 3) << 4);
    const int lrB     = ((lane >> 4) << 3) + (lane & 7);
    const u32 b_row64 = (u32)(wn * 64 + lrB) * 64;
    const u32 cB16    = (u32)(((lane >> 3) & 1) << 4);
    const u32 xB      = (u32)(((lrB >> 1) & 3) << 4);

    float acc[2][8][4];
#pragma unroll
    for (int mt = 0; mt < 2; mt++)
#pragma unroll
        for (int nt = 0; nt < 8; nt++)
#pragma unroll
            for (int q = 0; q < 4; q++) acc[mt][nt][q] = 0.f;

    load_stage(0, 0); CP_COMMIT();
    load_stage(1, 1); CP_COMMIT();

    for (int i = 0; i < NCH; i++) {
        if (i + 1 < NCH) { CP_WAIT(1); } else { CP_WAIT(0); }
        __syncthreads();                 // publish stage i; stage (i+2)%3 free
        if (i + 2 < NCH) { load_stage(i + 2, (i + 2) % 3); CP_COMMIT(); }

        const u32 s = sb + (u32)(i % 3) * STAGEB;

#pragma unroll
        for (int kt = 0; kt < 2; kt++) {
            const u32 ktb = (u32)kt * 32;
            u32 ah[2][4], al[2][4];
#pragma unroll
            for (int mt = 0; mt < 2; mt++) {
                u32 la = s + a_row64 + (u32)mt * 1024 + cA16 + ktb;
                LDSM4(ah[mt], la ^ xA);
                LDSM4(al[mt], (la + TILEB) ^ xA);
            }
            u32 bh[4][4], bl[4][4];
#pragma unroll
            for (int p = 0; p < 4; p++) {
                u32 lb = s + 2 * TILEB + b_row64 + (u32)p * 1024 + cB16 + ktb;
                LDSM4(bh[p], lb ^ xB);
                LDSM4(bl[p], (lb + TILEB) ^ xB);
            }
#pragma unroll
            for (int mt = 0; mt < 2; mt++)
#pragma unroll
                for (int nt = 0; nt < 8; nt++) {
                    const int p = nt >> 1, e = (nt & 1) * 2;
                    MMA16816(acc[mt][nt], ah[mt], bh[p][e], bh[p][e + 1]);
                    MMA16816(acc[mt][nt], ah[mt], bl[p][e], bl[p][e + 1]);
                    MMA16816(acc[mt][nt], al[mt], bh[p][e], bh[p][e + 1]);
                }
        }
    }

    // epilogue
#pragma unroll
    for (int mt = 0; mt < 2; mt++) {
        const int r0 = m0 + wm * 32 + mt * 16 + (lane >> 2);
#pragma unroll
        for (int nt = 0; nt < 8; nt++) {
            const int n = n0 + wn * 64 + nt * 8 + (lane & 3) * 2;
            if (EPI == 0) {
                float* p0 = C + (size_t)r0 * Nout + n;
                float* p1 = C + (size_t)(r0 + 8) * Nout + n;
                *(float2*)p0 = make_float2(acc[mt][nt][0], acc[mt][nt][1]);
                *(float2*)p1 = make_float2(acc[mt][nt][2], acc[mt][nt][3]);
            } else {
                const int sec = n >> 10;
                const int cc  = n & 1023;
                const int h   = cc >> 6, dd = cc & 63;
                __nv_bfloat16* bhp = (sec == 0) ? g_qh : (sec == 1) ? g_kh : g_vh;
                __nv_bfloat16* blp = (sec == 0) ? g_ql : (sec == 1) ? g_kl : g_vl;
                {
                    const int bb0 = r0 >> 11, tt0 = r0 & 2047;
                    size_t i0 = ((size_t)(bb0 * HH + h) * TT + tt0) * DD + dd;
                    u32 hi, lo;
                    split2(acc[mt][nt][0], acc[mt][nt][1], hi, lo);
                    *(u32*)(bhp + i0) = hi;  *(u32*)(blp + i0) = lo;
                }
                {
                    const int r1 = r0 + 8;
                    const int bb1 = r1 >> 11, tt1 = r1 & 2047;
                    size_t i1 = ((size_t)(bb1 * HH + h) * TT + tt1) * DD + dd;
                    u32 hi, lo;
                    split2(acc[mt][nt][2], acc[mt][nt][3], hi, lo);
                    *(u32*)(bhp + i1) = hi;  *(u32*)(blp + i1) = lo;
                }
            }
        }
    }
}

// ------------------------- tensor-core flash attention (3-stage KV) -------------------------
#define AROWB 144
#define KTL 64
#define ASTG (4 * KTL * AROWB)      // 36864: Kh, Kl, Vth, Vtl
#define QSZ  (2 * 128 * AROWB)      // 36864: Qh, Ql
#define ASMEM (QSZ + 3 * ASTG)      // 147456

__global__ void __launch_bounds__(256, 1) attn_tc()
{
    extern __shared__ char smem[];
    const u32 sb   = smem_u32(smem);
    const int tid  = threadIdx.x;
    const int lane = tid & 31;
    const int wid  = tid >> 5;
    const int qi   = (int)gridDim.x - 1 - (int)blockIdx.x;
    const int bh   = blockIdx.y;
    const int q0   = qi * 128;
    const int g    = lane >> 2, tg = lane & 3;
    const int wrow0 = q0 + wid * 16;

    // Q -> dedicated region
#pragma unroll
    for (int r = 0; r < 8; r++) {
        int ch  = tid + r * 256;
        int hl  = ch >> 10;
        int rem = ch & 1023;
        int row = rem >> 3, c = rem & 7;
        const __nv_bfloat16* src = (hl ? g_ql : g_qh) + ((size_t)bh * TT + q0 + row) * DD + c * 8;
        CP_ASYNC16(sb + hl * (128 * AROWB) + row * AROWB + c * 16, src);
    }
    CP_COMMIT();

    auto load_kv = [&](int kt, int stage) {
        const int j0 = kt * KTL;
        const u32 s = sb + QSZ + (u32)stage * ASTG;
#pragma unroll
        for (int r = 0; r < 8; r++) {
            int ch  = tid + r * 256;
            int mat = ch >> 9;
            int rem = ch & 511;
            int row = rem >> 3, c = rem & 7;
            const __nv_bfloat16* src;
            if      (mat == 0) src = g_kh  + ((size_t)bh * TT + j0 + row) * DD + c * 8;
            else if (mat == 1) src = g_kl  + ((size_t)bh * TT + j0 + row) * DD + c * 8;
            else if (mat == 2) src = g_vth + ((size_t)bh * DD + row) * TT + j0 + c * 8;
            else               src = g_vtl + ((size_t)bh * DD + row) * TT + j0 + c * 8;
            CP_ASYNC16(s + mat * (KTL * AROWB) + row * AROWB + c * 16, src);
        }
        CP_COMMIT();
    };

    const int nkt = 2 * qi + 2;
    load_kv(0, 0);
    if (nkt > 1) load_kv(1, 1);

    CP_WAIT(2);                  // Q done
    __syncthreads();

    u32 qh[4][4], ql[4][4];
    {
        const u32 qb = sb + (u32)(wid * 16 + (lane & 15)) * AROWB + ((lane >> 4) << 4);
#pragma unroll
        for (int ks = 0; ks < 4; ks++) {
            LDSM4(qh[ks], qb + ks * 32);
            LDSM4(ql[ks], qb + 128 * AROWB + ks * 32);
        }
    }

    float o[8][4];
#pragma unroll
    for (int nt = 0; nt < 8; nt++)
#pragma unroll
        for (int e = 0; e < 4; e++) o[nt][e] = 0.f;
    float m_lo = -1e30f, m_hi = -1e30f, l_lo = 0.f, l_hi = 0.f;

    const u32 boff = (u32)((((lane >> 4) << 3) + (lane & 7)) * AROWB + (((lane >> 3) & 1) << 4));

    for (int kt = 0; kt < nkt; kt++) {
        if (kt + 1 < nkt) { CP_WAIT(1); } else { CP_WAIT(0); }
        __syncthreads();             // publish stage kt; stage (kt+2)%3 free
        if (kt + 2 < nkt) load_kv(kt + 2, (kt + 2) % 3);

        const u32 s  = sb + QSZ + (u32)(kt % 3) * ASTG;
        const int j0 = kt * KTL;

        if (j0 <= wrow0 + 15) {
            float sacc[8][4];
#pragma unroll
            for (int nt = 0; nt < 8; nt++)
#pragma unroll
                for (int e = 0; e < 4; e++) sacc[nt][e] = 0.f;
#pragma unroll
            for (int p = 0; p < 4; p++) {
#pragma unroll
                for (int ks = 0; ks < 4; ks++) {
                    u32 kh[4], kl[4];
                    LDSM4(kh, s + (u32)p * (16 * AROWB) + boff + ks * 32);
                    LDSM4(kl, s + KTL * AROWB + (u32)p * (16 * AROWB) + boff + ks * 32);
                    MMA16816(sacc[2 * p],     qh[ks], kh[0], kh[1]);
                    MMA16816(sacc[2 * p],     ql[ks], kh[0], kh[1]);
                    MMA16816(sacc[2 * p],     qh[ks], kl[0], kl[1]);
                    MMA16816(sacc[2 * p + 1], qh[ks], kh[2], kh[3]);
                    MMA16816(sacc[2 * p + 1], ql[ks], kh[2], kh[3]);
                    MMA16816(sacc[2 * p + 1], qh[ks], kl[2], kl[3]);
                }
            }
            const int row_a = wrow0 + g;
            const bool diag = (j0 + 63 > wrow0);
            float tmax_lo = -1e30f, tmax_hi = -1e30f;
#pragma unroll
            for (int nt = 0; nt < 8; nt++) {
#pragma unroll
                for (int e = 0; e < 2; e++) {
                    int j = j0 + nt * 8 + tg * 2 + e;
                    float v0 = sacc[nt][e]     * 0.125f;
                    float v1 = sacc[nt][e + 2] * 0.125f;
                    if (diag) {
                        if (j > row_a)     v0 = -1e30f;
                        if (j > row_a + 8) v1 = -1e30f;
                    }
                    sacc[nt][e]     = v0;
                    sacc[nt][e + 2] = v1;
                    tmax_lo = fmaxf(tmax_lo, v0);
                    tmax_hi = fmaxf(tmax_hi, v1);
                }
            }
            tmax_lo = fmaxf(tmax_lo, __shfl_xor_sync(0xffffffffu, tmax_lo, 1));
            tmax_lo = fmaxf(tmax_lo, __shfl_xor_sync(0xffffffffu, tmax_lo, 2));
            tmax_hi = fmaxf(tmax_hi, __shfl_xor_sync(0xffffffffu, tmax_hi, 1));
            tmax_hi = fmaxf(tmax_hi, __shfl_xor_sync(0xffffffffu, tmax_hi, 2));

            float mn_lo = fmaxf(m_lo, tmax_lo);
            float mn_hi = fmaxf(m_hi, tmax_hi);
            float c_lo = __expf(m_lo - mn_lo);
            float c_hi = __expf(m_hi - mn_hi);
            m_lo = mn_lo; m_hi = mn_hi;
            l_lo *= c_lo; l_hi *= c_hi;
#pragma unroll
            for (int nt = 0; nt < 8; nt++) {
                o[nt][0] *= c_lo; o[nt][1] *= c_lo;
                o[nt][2] *= c_hi; o[nt][3] *= c_hi;
            }
            u32 ph[4][4], pl[4][4];
            float rs_lo = 0.f, rs_hi = 0.f;
#pragma unroll
            for (int kk = 0; kk < 4; kk++) {
#pragma unroll
                for (int half = 0; half < 2; half++) {
                    const int t2 = 2 * kk + half;
                    float p0 = __expf(sacc[t2][0] - m_lo);
                    float p1 = __expf(sacc[t2][1] - m_lo);
                    float p2 = __expf(sacc[t2][2] - m_hi);
                    float p3 = __expf(sacc[t2][3] - m_hi);
                    rs_lo += p0 + p1;  rs_hi += p2 + p3;
                    split2(p0, p1, ph[kk][2 * half],     pl[kk][2 * half]);
                    split2(p2, p3, ph[kk][2 * half + 1], pl[kk][2 * half + 1]);
                }
            }
            rs_lo += __shfl_xor_sync(0xffffffffu, rs_lo, 1);
            rs_lo += __shfl_xor_sync(0xffffffffu, rs_lo, 2);
            rs_hi += __shfl_xor_sync(0xffffffffu, rs_hi, 1);
            rs_hi += __shfl_xor_sync(0xffffffffu, rs_hi, 2);
            l_lo += rs_lo;  l_hi += rs_hi;
#pragma unroll
            for (int pd = 0; pd < 4; pd++) {
#pragma unroll
                for (int kk = 0; kk < 4; kk++) {
                    u32 vh[4], vl[4];
                    LDSM4(vh, s + 2 * KTL * AROWB + (u32)pd * (16 * AROWB) + boff + kk * 32);
                    LDSM4(vl, s + 3 * KTL * AROWB + (u32)pd * (16 * AROWB) + boff + kk * 32);
                    MMA16816(o[2 * pd],     ph[kk], vh[0], vh[1]);
                    MMA16816(o[2 * pd],     pl[kk], vh[0], vh[1]);
                    MMA16816(o[2 * pd],     ph[kk], vl[0], vl[1]);
                    MMA16816(o[2 * pd + 1], ph[kk], vh[2], vh[3]);
                    MMA16816(o[2 * pd + 1], pl[kk], vh[2], vh[3]);
                    MMA16816(o[2 * pd + 1], ph[kk], vl[2], vl[3]);
                }
            }
        }
    }

    const float inv_lo = 1.f / l_lo;
    const float inv_hi = 1.f / l_hi;
    const int bb = bh >> 4, h = bh & 15;
    const int t_a = wrow0 + g;
#pragma unroll
    for (int nt = 0; nt < 8; nt++) {
        const int c = h * DD + nt * 8 + tg * 2;
        size_t i0 = ((size_t)bb * TT + t_a) * CCH + c;
        size_t i1 = ((size_t)bb * TT + t_a + 8) * CCH + c;
        u32 hi, lo;
        split2(o[nt][0] * inv_lo, o[nt][1] * inv_lo, hi, lo);
        *(u32*)(g_yh + i0) = hi;  *(u32*)(g_yl + i0) = lo;
        split2(o[nt][2] * inv_hi, o[nt][3] * inv_hi, hi, lo);
        *(u32*)(g_yh + i1) = hi;  *(u32*)(g_yl + i1) = lo;
    }
}

// ---------------------------------------------------------------------------
extern "C" void kernel_launch(void* const* d_in, const int* in_sizes, int n_in,
                              void* d_out, int out_size)
{
    const float* x      = (const float*)d_in[0];
    const float* w_qkv  = (const float*)d_in[1];
    const float* w_proj = (const float*)d_in[2];
    float* out          = (float*)d_out;

    cudaFuncSetAttribute(gemm_bf16s<1>, cudaFuncAttributeMaxDynamicSharedMemorySize, GSMEM);
    cudaFuncSetAttribute(gemm_bf16s<0>, cudaFuncAttributeMaxDynamicSharedMemorySize, GSMEM);
    cudaFuncSetAttribute(attn_tc, cudaFuncAttributeMaxDynamicSharedMemorySize, ASMEM);

    __nv_bfloat16 *xh, *xl, *yh, *yl, *wqh, *wql, *wph, *wpl;
    cudaGetSymbolAddress((void**)&xh,  g_xh);
    cudaGetSymbolAddress((void**)&xl,  g_xl);
    cudaGetSymbolAddress((void**)&yh,  g_yh);
    cudaGetSymbolAddress((void**)&yl,  g_yl);
    cudaGetSymbolAddress((void**)&wqh, g_wqh);
    cudaGetSymbolAddress((void**)&wql, g_wql);
    cudaGetSymbolAddress((void**)&wph, g_wph);
    cudaGetSymbolAddress((void**)&wpl, g_wpl);

    transpose_split<<<dim3(3 * CCH / 32, KDIM / 32), 256>>>(w_qkv, wqh, wql, 3 * CCH);
    transpose_split<<<dim3(CCH / 32, KDIM / 32), 256>>>(w_proj, wph, wpl, CCH);
    split_kernel<<<(MM * KDIM / 4 + 255) / 256, 256>>>(x, xh, xl, MM * KDIM / 4);

    gemm_bf16s<1><<<dim3(3 * CCH / 128, MM / 128), 256, GSMEM>>>(xh, xl, wqh, wql, nullptr, 3 * CCH);

    vt_kernel<<<dim3(TT / 64, BHN), 256>>>();

    attn_tc<<<dim3(TT / 128, BHN), 256, ASMEM>>>();

    gemm_bf16s<0><<<dim3(CCH / 128, MM / 128), 256, GSMEM>>>(yh, yl, wph, wpl, out, CCH);
}